// round 1
// baseline (speedup 1.0000x reference)
#include <cuda_runtime.h>
#include <math.h>

#define NB 4
#define NS 2048
#define ND 768
#define NH 8
#define NHD 96
#define NM (NB*NS)

#define NEGV (-1e9f)

// ---------------- scratch (device globals; no allocations allowed) ----------
__device__ float g_xn[NM*ND];
__device__ float g_q [NM*ND];
__device__ float g_k [NM*ND];
__device__ float g_v [NM*ND];
__device__ float g_ao[NM*ND];
__device__ int   g_mask_kind; // 0=u8/i8, 1=i32, 2=f32

__device__ __forceinline__ float mask_val(const void* m, int i) {
    int kind = g_mask_kind;
    if (kind == 0) return ((const unsigned char*)m)[i] ? 1.f : 0.f;
    if (kind == 1) return ((const int*)m)[i]          ? 1.f : 0.f;
    return (((const float*)m)[i] != 0.f)              ? 1.f : 0.f;
}

// Detect mask dtype from byte patterns (values are 0/1):
//  u8 : nonzero bytes at offsets i%4==1
//  f32: 1.0f = [00 00 80 3F] -> nonzero at i%4 in {2,3}, zero at i%4==1
//  i32: 1    = [01 00 00 00] -> zero at all i%4!=0
__global__ void detect_mask_kernel(const unsigned char* __restrict__ p) {
    if (threadIdx.x != 0 || blockIdx.x != 0) return;
    int has1 = 0, has23 = 0;
    for (int i = 0; i < 4096; i += 4) {
        if (p[i+1]) has1 = 1;
        if (p[i+2] | p[i+3]) has23 = 1;
    }
    g_mask_kind = has1 ? 0 : (has23 ? 2 : 1);
}

// ---------------- LayerNorm: one block per row of 768 -----------------------
__global__ __launch_bounds__(256) void ln_kernel(
    const float* __restrict__ x, const float* __restrict__ g,
    const float* __restrict__ b, float* __restrict__ y)
{
    int row = blockIdx.x;
    const float* xr = x + (size_t)row*ND;
    float* yr = y + (size_t)row*ND;
    int t = threadIdx.x;
    float v0 = xr[t], v1 = xr[t+256], v2 = xr[t+512];
    float s  = v0+v1+v2;
    float sq = v0*v0+v1*v1+v2*v2;
    #pragma unroll
    for (int o = 16; o > 0; o >>= 1) {
        s  += __shfl_xor_sync(0xffffffffu, s,  o);
        sq += __shfl_xor_sync(0xffffffffu, sq, o);
    }
    __shared__ float ss[8], sqq[8];
    __shared__ float smu, srs;
    int w = t >> 5;
    if ((t & 31) == 0) { ss[w] = s; sqq[w] = sq; }
    __syncthreads();
    if (t == 0) {
        float S = 0.f, Q = 0.f;
        #pragma unroll
        for (int i = 0; i < 8; i++) { S += ss[i]; Q += sqq[i]; }
        float mu  = S * (1.f/ND);
        float var = Q * (1.f/ND) - mu*mu;
        smu = mu; srs = rsqrtf(var + 1e-5f);
    }
    __syncthreads();
    float mu = smu, rs = srs;
    yr[t]     = (v0-mu)*rs*g[t]     + b[t];
    yr[t+256] = (v1-mu)*rs*g[t+256] + b[t+256];
    yr[t+512] = (v2-mu)*rs*g[t+512] + b[t+512];
}

// ---------------- Tiled SGEMM: C[M,768] = A[M,768] @ W[768,768]^T + bias ----
// W layout (E,D) row-major; inner dim contiguous for both A and W (NT gemm).
// Block 128x128, K-tile 16, 8x8 thread tiles, 256 threads.
// blockIdx.z selects among 3 (W,bias,C) sets (fused QKV). mask!=null:
// multiply output row by mask (O-projection epilogue).
#define BM 128
#define BN 128
#define BK 16
#define AP 132

__global__ __launch_bounds__(256, 2) void gemm_nt(
    const float* __restrict__ A,
    const float* __restrict__ W0, const float* __restrict__ B0, float* __restrict__ C0,
    const float* __restrict__ W1, const float* __restrict__ B1, float* __restrict__ C1,
    const float* __restrict__ W2, const float* __restrict__ B2, float* __restrict__ C2,
    const void* __restrict__ mask)
{
    const float* W    = (blockIdx.z == 0) ? W0 : (blockIdx.z == 1) ? W1 : W2;
    const float* bias = (blockIdx.z == 0) ? B0 : (blockIdx.z == 1) ? B1 : B2;
    float*       C    = (blockIdx.z == 0) ? C0 : (blockIdx.z == 1) ? C1 : C2;

    __shared__ __align__(16) float As[BK*AP];
    __shared__ __align__(16) float Bs[BK*AP];

    int tid = threadIdx.x;
    int bm = blockIdx.y*BM, bn = blockIdx.x*BN;
    int lr = tid >> 2;            // 0..63
    int lc = (tid & 3) << 2;      // 0,4,8,12
    const float* Ag  = A + (size_t)(bm+lr)*ND + lc;
    const float* Ag2 = Ag + (size_t)64*ND;
    const float* Wg  = W + (size_t)(bn+lr)*ND + lc;
    const float* Wg2 = Wg + (size_t)64*ND;
    int ty = tid >> 4, tx = tid & 15;

    float acc[8][8];
    #pragma unroll
    for (int i = 0; i < 8; i++)
        #pragma unroll
        for (int j = 0; j < 8; j++) acc[i][j] = 0.f;

    for (int k0 = 0; k0 < ND; k0 += BK) {
        float4 a0 = *(const float4*)(Ag  + k0);
        float4 a1 = *(const float4*)(Ag2 + k0);
        float4 w0 = *(const float4*)(Wg  + k0);
        float4 w1 = *(const float4*)(Wg2 + k0);
        __syncthreads();
        As[(lc+0)*AP+lr]    = a0.x; As[(lc+1)*AP+lr]    = a0.y;
        As[(lc+2)*AP+lr]    = a0.z; As[(lc+3)*AP+lr]    = a0.w;
        As[(lc+0)*AP+lr+64] = a1.x; As[(lc+1)*AP+lr+64] = a1.y;
        As[(lc+2)*AP+lr+64] = a1.z; As[(lc+3)*AP+lr+64] = a1.w;
        Bs[(lc+0)*AP+lr]    = w0.x; Bs[(lc+1)*AP+lr]    = w0.y;
        Bs[(lc+2)*AP+lr]    = w0.z; Bs[(lc+3)*AP+lr]    = w0.w;
        Bs[(lc+0)*AP+lr+64] = w1.x; Bs[(lc+1)*AP+lr+64] = w1.y;
        Bs[(lc+2)*AP+lr+64] = w1.z; Bs[(lc+3)*AP+lr+64] = w1.w;
        __syncthreads();
        #pragma unroll
        for (int k = 0; k < BK; k++) {
            float4 af0 = *(const float4*)&As[k*AP + (ty<<3)];
            float4 af1 = *(const float4*)&As[k*AP + (ty<<3) + 4];
            float4 bf0 = *(const float4*)&Bs[k*AP + (tx<<3)];
            float4 bf1 = *(const float4*)&Bs[k*AP + (tx<<3) + 4];
            float a[8] = {af0.x,af0.y,af0.z,af0.w,af1.x,af1.y,af1.z,af1.w};
            float bb[8] = {bf0.x,bf0.y,bf0.z,bf0.w,bf1.x,bf1.y,bf1.z,bf1.w};
            #pragma unroll
            for (int i = 0; i < 8; i++)
                #pragma unroll
                for (int j = 0; j < 8; j++)
                    acc[i][j] += a[i]*bb[j];
        }
    }

    #pragma unroll
    for (int i = 0; i < 8; i++) {
        int m = bm + (ty<<3) + i;
        float mf = mask ? mask_val(mask, m) : 1.f;
        int n0 = bn + (tx<<3);
        float* cr = &C[(size_t)m*ND + n0];
        float4 r0 = make_float4((acc[i][0]+bias[n0+0])*mf, (acc[i][1]+bias[n0+1])*mf,
                                (acc[i][2]+bias[n0+2])*mf, (acc[i][3]+bias[n0+3])*mf);
        float4 r1 = make_float4((acc[i][4]+bias[n0+4])*mf, (acc[i][5]+bias[n0+5])*mf,
                                (acc[i][6]+bias[n0+6])*mf, (acc[i][7]+bias[n0+7])*mf);
        *(float4*)(cr)   = r0;
        *(float4*)(cr+4) = r1;
    }
}

// ---------------- Flash-style anchor-masked attention ------------------------
// grid (S/64, H, B), 256 threads. 64-query x 64-key tiles, HD=96.
// 4 threads per query row: cq selects 16 score cols / 24 output cols.
#define Q_STR 100
#define KT_STR 68
#define V_STR 100
#define P_STR 65
#define OFF_Q  0
#define OFF_KT (64*Q_STR)                 // 6400
#define OFF_V  (OFF_KT + NHD*KT_STR)      // 12928
#define OFF_P  (OFF_V + 64*V_STR)         // 19328
#define OFF_KM (OFF_P + 64*P_STR)         // 23488
#define ATT_SMEM_FLOATS (OFF_KM + 64)     // 23552 floats = 94208 B

__global__ __launch_bounds__(256) void attn_kernel(
    const float* __restrict__ Q, const float* __restrict__ K,
    const float* __restrict__ V, const void* __restrict__ mask,
    float* __restrict__ O)
{
    extern __shared__ __align__(16) float smf[];
    float* qs = smf + OFF_Q;    // [64][100] q rows
    float* kT = smf + OFF_KT;   // [96][68]  k transposed (d-major)
    float* vs = smf + OFF_V;    // [64][100] v rows
    float* ps = smf + OFF_P;    // [64][65]  probabilities
    float* km = smf + OFF_KM;   // [64]      key mask (1/0)

    int tid = threadIdx.x;
    int qt = blockIdx.x, h = blockIdx.y, b = blockIdx.z;
    int q0 = qt*64;
    int r  = tid >> 2;          // query row 0..63
    int cq = tid & 3;
    int c0 = cq << 4;           // score col base
    int vcol = cq * 24;         // output col base

    const float* qg = Q + ((size_t)(b*NS)+q0)*ND + h*NHD;
    for (int f = tid; f < 64*24; f += 256) {
        int rr = f/24, c4 = (f%24)<<2;
        *(float4*)&qs[rr*Q_STR + c4] = *(const float4*)(qg + (size_t)rr*ND + c4);
    }

    float m_r = -INFINITY, l_r = 0.f;
    float acc[24];
    #pragma unroll
    for (int j = 0; j < 24; j++) acc[j] = 0.f;
    const float scale = 0.1020620726159658f; // 1/sqrt(96)

    for (int kt = 0; kt < NS/64; kt++) {
        int k0 = kt*64;
        __syncthreads();  // previous tile fully consumed (also covers qs load)
        const float* kg = K + ((size_t)(b*NS)+k0)*ND + h*NHD;
        const float* vg = V + ((size_t)(b*NS)+k0)*ND + h*NHD;
        for (int f = tid; f < 64*24; f += 256) {
            int rr = f/24, c4 = (f%24)<<2;
            float4 kv = *(const float4*)(kg + (size_t)rr*ND + c4);
            kT[(c4+0)*KT_STR + rr] = kv.x;
            kT[(c4+1)*KT_STR + rr] = kv.y;
            kT[(c4+2)*KT_STR + rr] = kv.z;
            kT[(c4+3)*KT_STR + rr] = kv.w;
            *(float4*)&vs[rr*V_STR + c4] = *(const float4*)(vg + (size_t)rr*ND + c4);
        }
        if (tid < 64) km[tid] = mask_val(mask, b*NS + k0 + tid);
        __syncthreads();

        // ---- scores: 16 per thread over HD=96 ----
        float sc[16];
        #pragma unroll
        for (int i = 0; i < 16; i++) sc[i] = 0.f;
        #pragma unroll
        for (int d = 0; d < NHD; d += 4) {
            float4 qv = *(const float4*)&qs[r*Q_STR + d];
            #pragma unroll
            for (int j = 0; j < 4; j++) {
                float qd = (j==0)?qv.x:(j==1)?qv.y:(j==2)?qv.z:qv.w;
                const float* kr = &kT[(d+j)*KT_STR + c0];
                float4 k0v = *(const float4*)(kr);
                float4 k1v = *(const float4*)(kr+4);
                float4 k2v = *(const float4*)(kr+8);
                float4 k3v = *(const float4*)(kr+12);
                sc[0] += qd*k0v.x; sc[1] += qd*k0v.y; sc[2] += qd*k0v.z; sc[3] += qd*k0v.w;
                sc[4] += qd*k1v.x; sc[5] += qd*k1v.y; sc[6] += qd*k1v.z; sc[7] += qd*k1v.w;
                sc[8] += qd*k2v.x; sc[9] += qd*k2v.y; sc[10]+= qd*k2v.z; sc[11]+= qd*k2v.w;
                sc[12]+= qd*k3v.x; sc[13]+= qd*k3v.y; sc[14]+= qd*k3v.z; sc[15]+= qd*k3v.w;
            }
        }

        // ---- mask + online softmax (group of 4 lanes per row) ----
        float mymax = -INFINITY;
        #pragma unroll
        for (int i = 0; i < 16; i++) {
            float s = (km[c0+i] != 0.f) ? sc[i]*scale : NEGV;
            sc[i] = s;
            mymax = fmaxf(mymax, s);
        }
        mymax = fmaxf(mymax, __shfl_xor_sync(0xffffffffu, mymax, 1));
        mymax = fmaxf(mymax, __shfl_xor_sync(0xffffffffu, mymax, 2));
        float mnew  = fmaxf(m_r, mymax);
        float alpha = __expf(m_r - mnew);
        float psum = 0.f;
        #pragma unroll
        for (int i = 0; i < 16; i++) {
            float p = __expf(sc[i] - mnew);
            ps[r*P_STR + c0 + i] = p;
            psum += p;
        }
        psum += __shfl_xor_sync(0xffffffffu, psum, 1);
        psum += __shfl_xor_sync(0xffffffffu, psum, 2);
        l_r = l_r*alpha + psum;
        m_r = mnew;
        #pragma unroll
        for (int j = 0; j < 24; j++) acc[j] *= alpha;
        __syncwarp();

        // ---- out += P @ V (24 cols per thread) ----
        #pragma unroll 4
        for (int kk = 0; kk < 64; kk++) {
            float p = ps[r*P_STR + kk];
            const float* vr = &vs[kk*V_STR + vcol];
            float4 v0 = *(const float4*)(vr);
            float4 v1 = *(const float4*)(vr+4);
            float4 v2 = *(const float4*)(vr+8);
            float4 v3 = *(const float4*)(vr+12);
            float4 v4 = *(const float4*)(vr+16);
            float4 v5 = *(const float4*)(vr+20);
            acc[0] += p*v0.x; acc[1] += p*v0.y; acc[2] += p*v0.z; acc[3] += p*v0.w;
            acc[4] += p*v1.x; acc[5] += p*v1.y; acc[6] += p*v1.z; acc[7] += p*v1.w;
            acc[8] += p*v2.x; acc[9] += p*v2.y; acc[10]+= p*v2.z; acc[11]+= p*v2.w;
            acc[12]+= p*v3.x; acc[13]+= p*v3.y; acc[14]+= p*v3.z; acc[15]+= p*v3.w;
            acc[16]+= p*v4.x; acc[17]+= p*v4.y; acc[18]+= p*v4.z; acc[19]+= p*v4.w;
            acc[20]+= p*v5.x; acc[21]+= p*v5.y; acc[22]+= p*v5.z; acc[23]+= p*v5.w;
        }
    }

    float inv = 1.f / l_r;
    float* og = O + ((size_t)(b*NS)+q0+r)*ND + h*NHD + vcol;
    #pragma unroll
    for (int j = 0; j < 24; j += 4) {
        *(float4*)(og+j) = make_float4(acc[j]*inv, acc[j+1]*inv, acc[j+2]*inv, acc[j+3]*inv);
    }
}

// ---------------- launch ------------------------------------------------------
extern "C" void kernel_launch(void* const* d_in, const int* in_sizes, int n_in,
                              void* d_out, int out_size)
{
    const float* hs  = (const float*)d_in[0];
    const void*  am  = d_in[1];
    const float* lng = (const float*)d_in[2];
    const float* lnb = (const float*)d_in[3];
    const float* Wq  = (const float*)d_in[4];
    const float* bq  = (const float*)d_in[5];
    const float* Wk  = (const float*)d_in[6];
    const float* bk  = (const float*)d_in[7];
    const float* Wv  = (const float*)d_in[8];
    const float* bv  = (const float*)d_in[9];
    const float* Wo  = (const float*)d_in[10];
    const float* bo  = (const float*)d_in[11];
    float* out = (float*)d_out;

    float *xn, *q, *k, *v, *ao;
    cudaGetSymbolAddress((void**)&xn, g_xn);
    cudaGetSymbolAddress((void**)&q,  g_q);
    cudaGetSymbolAddress((void**)&k,  g_k);
    cudaGetSymbolAddress((void**)&v,  g_v);
    cudaGetSymbolAddress((void**)&ao, g_ao);

    cudaFuncSetAttribute(attn_kernel, cudaFuncAttributeMaxDynamicSharedMemorySize,
                         ATT_SMEM_FLOATS * 4);

    detect_mask_kernel<<<1, 1>>>((const unsigned char*)am);
    ln_kernel<<<NM, 256>>>(hs, lng, lnb, xn);

    dim3 gqkv(ND/BN, NM/BM, 3);
    gemm_nt<<<gqkv, 256>>>(xn, Wq, bq, q, Wk, bk, k, Wv, bv, v, nullptr);

    attn_kernel<<<dim3(NS/64, NH, NB), 256, ATT_SMEM_FLOATS*4>>>(q, k, v, am, ao);

    dim3 go(ND/BN, NM/BM, 1);
    gemm_nt<<<go, 256>>>(ao, Wo, bo, out, Wo, bo, out, Wo, bo, out, am);
}

// round 3
// speedup vs baseline: 2.9584x; 2.9584x over previous
#include <cuda_runtime.h>
#include <math.h>

#define NB 4
#define NS 2048
#define ND 768
#define NH 8
#define NHD 96
#define NM (NB*NS)

#define NEGV (-1e9f)

// ---------------- scratch (device globals; no allocations allowed) ----------
__device__ float g_xn[NM*ND];
__device__ float g_q [NM*ND];
__device__ float g_k [NM*ND];
__device__ float g_v [NM*ND];
__device__ float g_ao[NM*ND];
__device__ int   g_idx[NM];     // per batch: compacted j -> original s
__device__ int   g_cnt[NB];     // anchors per batch
__device__ int   g_mask_kind;   // 0=u8/i8, 1=i32, 2=f32

__device__ __forceinline__ float mask_val(const void* m, int i) {
    int kind = g_mask_kind;
    if (kind == 0) return ((const unsigned char*)m)[i] ? 1.f : 0.f;
    if (kind == 1) return ((const int*)m)[i]          ? 1.f : 0.f;
    return (((const float*)m)[i] != 0.f)              ? 1.f : 0.f;
}

// Detect mask dtype from byte patterns (values are 0/1):
//  u8 : nonzero bytes at offsets i%4==1
//  f32: 1.0f = [00 00 80 3F] -> nonzero at i%4 in {2,3}, zero at i%4==1
//  i32: 1    = [01 00 00 00] -> zero at all i%4!=0
__global__ void detect_mask_kernel(const unsigned char* __restrict__ p) {
    if (threadIdx.x != 0 || blockIdx.x != 0) return;
    int has1 = 0, has23 = 0;
    for (int i = 0; i < 4096; i += 4) {
        if (p[i+1]) has1 = 1;
        if (p[i+2] | p[i+3]) has23 = 1;
    }
    g_mask_kind = has1 ? 0 : (has23 ? 2 : 1);
}

// ---------------- compaction: stable index list of anchor positions ---------
// one block of 256 threads per batch; each thread scans 8 consecutive entries.
__global__ __launch_bounds__(256) void compact_kernel(const void* __restrict__ mask) {
    int b = blockIdx.x;
    int tid = threadIdx.x;
    int base = b * NS;
    int s0 = tid * 8;
    int bits[8];
    int c = 0;
    #pragma unroll
    for (int e = 0; e < 8; e++) {
        bits[e] = (mask_val(mask, base + s0 + e) != 0.f) ? 1 : 0;
        c += bits[e];
    }
    // inclusive warp scan
    int lane = tid & 31, w = tid >> 5;
    int v = c;
    #pragma unroll
    for (int o = 1; o < 32; o <<= 1) {
        int t = __shfl_up_sync(0xffffffffu, v, o);
        if (lane >= o) v += t;
    }
    __shared__ int ws[8];
    if (lane == 31) ws[w] = v;
    __syncthreads();
    int wbase = 0;
    for (int i = 0; i < w; i++) wbase += ws[i];
    int p = wbase + v - c;  // exclusive prefix
    #pragma unroll
    for (int e = 0; e < 8; e++) {
        if (bits[e]) g_idx[base + p++] = s0 + e;
    }
    if (tid == 255) g_cnt[b] = p;
}

// ---------------- zero the output tensor ------------------------------------
__global__ __launch_bounds__(256) void zero_kernel(float4* __restrict__ out) {
    out[(size_t)blockIdx.x * 256 + threadIdx.x] = make_float4(0.f, 0.f, 0.f, 0.f);
}

// ---------------- LayerNorm + gather: compacted anchor rows only ------------
__global__ __launch_bounds__(256) void ln_kernel(
    const float* __restrict__ x, const float* __restrict__ g,
    const float* __restrict__ b, float* __restrict__ y)
{
    int slot = blockIdx.x;
    int bb = slot >> 11, j = slot & (NS-1);
    if (j >= g_cnt[bb]) return;
    int src = (bb << 11) + g_idx[slot];
    const float* xr = x + (size_t)src*ND;
    float* yr = y + (size_t)slot*ND;
    int t = threadIdx.x;
    float v0 = xr[t], v1 = xr[t+256], v2 = xr[t+512];
    float s  = v0+v1+v2;
    float sq = v0*v0+v1*v1+v2*v2;
    #pragma unroll
    for (int o = 16; o > 0; o >>= 1) {
        s  += __shfl_xor_sync(0xffffffffu, s,  o);
        sq += __shfl_xor_sync(0xffffffffu, sq, o);
    }
    __shared__ float ss[8], sqq[8];
    __shared__ float smu, srs;
    int w = t >> 5;
    if ((t & 31) == 0) { ss[w] = s; sqq[w] = sq; }
    __syncthreads();
    if (t == 0) {
        float S = 0.f, Q = 0.f;
        #pragma unroll
        for (int i = 0; i < 8; i++) { S += ss[i]; Q += sqq[i]; }
        float mu  = S * (1.f/ND);
        float var = Q * (1.f/ND) - mu*mu;
        smu = mu; srs = rsqrtf(var + 1e-5f);
    }
    __syncthreads();
    float mu = smu, rs = srs;
    yr[t]     = (v0-mu)*rs*g[t]     + b[t];
    yr[t+256] = (v1-mu)*rs*g[t+256] + b[t+256];
    yr[t+512] = (v2-mu)*rs*g[t+512] + b[t+512];
}

// ---------------- Tiled SGEMM on compacted rows ------------------------------
// C[slot,768] = A[slot,768] @ W[768,768]^T + bias, slots = b*2048 + j, j<cnt[b].
// Blocks fully past cnt exit; partial blocks clamp A-row loads.
// scatter=1: store to out row b*2048+idx[j] (O-projection epilogue).
#define BM 128
#define BN 128
#define BK 16
#define AP 132

__global__ __launch_bounds__(256, 2) void gemm_nt(
    const float* __restrict__ A,
    const float* __restrict__ W0, const float* __restrict__ B0, float* __restrict__ C0,
    const float* __restrict__ W1, const float* __restrict__ B1, float* __restrict__ C1,
    const float* __restrict__ W2, const float* __restrict__ B2, float* __restrict__ C2,
    int scatter)
{
    const float* W    = (blockIdx.z == 0) ? W0 : (blockIdx.z == 1) ? W1 : W2;
    const float* bias = (blockIdx.z == 0) ? B0 : (blockIdx.z == 1) ? B1 : B2;
    float*       C    = (blockIdx.z == 0) ? C0 : (blockIdx.z == 1) ? C1 : C2;

    int bm = blockIdx.y*BM, bn = blockIdx.x*BN;
    int bb = bm >> 11, j0 = bm & (NS-1);
    int cntb = g_cnt[bb];
    if (j0 >= cntb) return;

    __shared__ __align__(16) float As[BK*AP];
    __shared__ __align__(16) float Bs[BK*AP];

    int tid = threadIdx.x;
    int lr = tid >> 2;            // 0..63
    int lc = (tid & 3) << 2;      // 0,4,8,12
    int jr1 = min(j0 + lr,      cntb - 1);
    int jr2 = min(j0 + lr + 64, cntb - 1);
    const float* Ag  = A + (size_t)((bb<<11) + jr1)*ND + lc;
    const float* Ag2 = A + (size_t)((bb<<11) + jr2)*ND + lc;
    const float* Wg  = W + (size_t)(bn+lr)*ND + lc;
    const float* Wg2 = Wg + (size_t)64*ND;
    int ty = tid >> 4, tx = tid & 15;

    float acc[8][8];
    #pragma unroll
    for (int i = 0; i < 8; i++)
        #pragma unroll
        for (int j = 0; j < 8; j++) acc[i][j] = 0.f;

    for (int k0 = 0; k0 < ND; k0 += BK) {
        float4 a0 = *(const float4*)(Ag  + k0);
        float4 a1 = *(const float4*)(Ag2 + k0);
        float4 w0 = *(const float4*)(Wg  + k0);
        float4 w1 = *(const float4*)(Wg2 + k0);
        __syncthreads();
        As[(lc+0)*AP+lr]    = a0.x; As[(lc+1)*AP+lr]    = a0.y;
        As[(lc+2)*AP+lr]    = a0.z; As[(lc+3)*AP+lr]    = a0.w;
        As[(lc+0)*AP+lr+64] = a1.x; As[(lc+1)*AP+lr+64] = a1.y;
        As[(lc+2)*AP+lr+64] = a1.z; As[(lc+3)*AP+lr+64] = a1.w;
        Bs[(lc+0)*AP+lr]    = w0.x; Bs[(lc+1)*AP+lr]    = w0.y;
        Bs[(lc+2)*AP+lr]    = w0.z; Bs[(lc+3)*AP+lr]    = w0.w;
        Bs[(lc+0)*AP+lr+64] = w1.x; Bs[(lc+1)*AP+lr+64] = w1.y;
        Bs[(lc+2)*AP+lr+64] = w1.z; Bs[(lc+3)*AP+lr+64] = w1.w;
        __syncthreads();
        #pragma unroll
        for (int k = 0; k < BK; k++) {
            float4 af0 = *(const float4*)&As[k*AP + (ty<<3)];
            float4 af1 = *(const float4*)&As[k*AP + (ty<<3) + 4];
            float4 bf0 = *(const float4*)&Bs[k*AP + (tx<<3)];
            float4 bf1 = *(const float4*)&Bs[k*AP + (tx<<3) + 4];
            float a[8] = {af0.x,af0.y,af0.z,af0.w,af1.x,af1.y,af1.z,af1.w};
            float bb2[8] = {bf0.x,bf0.y,bf0.z,bf0.w,bf1.x,bf1.y,bf1.z,bf1.w};
            #pragma unroll
            for (int i = 0; i < 8; i++)
                #pragma unroll
                for (int j = 0; j < 8; j++)
                    acc[i][j] += a[i]*bb2[j];
        }
    }

    #pragma unroll
    for (int i = 0; i < 8; i++) {
        int j = j0 + (ty<<3) + i;
        int n0 = bn + (tx<<3);
        float4 r0 = make_float4(acc[i][0]+bias[n0+0], acc[i][1]+bias[n0+1],
                                acc[i][2]+bias[n0+2], acc[i][3]+bias[n0+3]);
        float4 r1 = make_float4(acc[i][4]+bias[n0+4], acc[i][5]+bias[n0+5],
                                acc[i][6]+bias[n0+6], acc[i][7]+bias[n0+7]);
        if (scatter) {
            if (j < cntb) {
                int orow = (bb<<11) + g_idx[(bb<<11) + j];
                float* cr = &C[(size_t)orow*ND + n0];
                *(float4*)(cr)   = r0;
                *(float4*)(cr+4) = r1;
            }
        } else {
            float* cr = &C[(size_t)((bb<<11)+j)*ND + n0];
            *(float4*)(cr)   = r0;
            *(float4*)(cr+4) = r1;
        }
    }
}

// ---------------- Flash-style attention on compacted rows (no mask!) ---------
// grid (S/64, H, B), 256 threads. 64-query x 64-key tiles, HD=96.
// 4 threads per query row: cq selects 16 score cols / 24 output cols.
#define Q_STR 100
#define KT_STR 68
#define V_STR 100
#define P_STR 65
#define OFF_Q  0
#define OFF_KT (64*Q_STR)                 // 6400
#define OFF_V  (OFF_KT + NHD*KT_STR)      // 12928
#define OFF_P  (OFF_V + 64*V_STR)         // 19328
#define ATT_SMEM_FLOATS (OFF_P + 64*P_STR) // 23488 floats = 93952 B

__global__ __launch_bounds__(256) void attn_kernel(
    const float* __restrict__ Q, const float* __restrict__ K,
    const float* __restrict__ V, float* __restrict__ O)
{
    extern __shared__ __align__(16) float smf[];
    float* qs = smf + OFF_Q;    // [64][100] q rows
    float* kT = smf + OFF_KT;   // [96][68]  k transposed (d-major)
    float* vs = smf + OFF_V;    // [64][100] v rows
    float* ps = smf + OFF_P;    // [64][65]  probabilities

    int tid = threadIdx.x;
    int qt = blockIdx.x, h = blockIdx.y, b = blockIdx.z;
    int cntb = g_cnt[b];
    int q0 = qt*64;
    if (q0 >= cntb) return;
    int ktiles = (cntb + 63) >> 6;

    int r  = tid >> 2;          // query row 0..63
    int cq = tid & 3;
    int c0 = cq << 4;           // score col base
    int vcol = cq * 24;         // output col base

    const float* qg = Q + ((size_t)(b*NS)+q0)*ND + h*NHD;
    for (int f = tid; f < 64*24; f += 256) {
        int rr = f/24, c4 = (f%24)<<2;
        *(float4*)&qs[rr*Q_STR + c4] = *(const float4*)(qg + (size_t)rr*ND + c4);
    }

    float m_r = -INFINITY, l_r = 0.f;
    float acc[24];
    #pragma unroll
    for (int j = 0; j < 24; j++) acc[j] = 0.f;
    const float scale = 0.1020620726159658f; // 1/sqrt(96)

    for (int kt = 0; kt < ktiles; kt++) {
        int k0 = kt*64;
        int valid = cntb - k0;    // >= 1; >= 64 for all but last tile
        __syncthreads();  // previous tile fully consumed (also covers qs load)
        const float* kg = K + ((size_t)(b*NS)+k0)*ND + h*NHD;
        const float* vg = V + ((size_t)(b*NS)+k0)*ND + h*NHD;
        for (int f = tid; f < 64*24; f += 256) {
            int rr = f/24, c4 = (f%24)<<2;
            float4 kv = *(const float4*)(kg + (size_t)rr*ND + c4);
            kT[(c4+0)*KT_STR + rr] = kv.x;
            kT[(c4+1)*KT_STR + rr] = kv.y;
            kT[(c4+2)*KT_STR + rr] = kv.z;
            kT[(c4+3)*KT_STR + rr] = kv.w;
            *(float4*)&vs[rr*V_STR + c4] = *(const float4*)(vg + (size_t)rr*ND + c4);
        }
        __syncthreads();

        // ---- scores: 16 per thread over HD=96 ----
        float sc[16];
        #pragma unroll
        for (int i = 0; i < 16; i++) sc[i] = 0.f;
        #pragma unroll
        for (int d = 0; d < NHD; d += 4) {
            float4 qv = *(const float4*)&qs[r*Q_STR + d];
            #pragma unroll
            for (int j = 0; j < 4; j++) {
                float qd = (j==0)?qv.x:(j==1)?qv.y:(j==2)?qv.z:qv.w;
                const float* kr = &kT[(d+j)*KT_STR + c0];
                float4 k0v = *(const float4*)(kr);
                float4 k1v = *(const float4*)(kr+4);
                float4 k2v = *(const float4*)(kr+8);
                float4 k3v = *(const float4*)(kr+12);
                sc[0] += qd*k0v.x; sc[1] += qd*k0v.y; sc[2] += qd*k0v.z; sc[3] += qd*k0v.w;
                sc[4] += qd*k1v.x; sc[5] += qd*k1v.y; sc[6] += qd*k1v.z; sc[7] += qd*k1v.w;
                sc[8] += qd*k2v.x; sc[9] += qd*k2v.y; sc[10]+= qd*k2v.z; sc[11]+= qd*k2v.w;
                sc[12]+= qd*k3v.x; sc[13]+= qd*k3v.y; sc[14]+= qd*k3v.z; sc[15]+= qd*k3v.w;
            }
        }

        // ---- online softmax (group of 4 lanes per row); pad cols -> -1e9 ----
        float mymax = -INFINITY;
        #pragma unroll
        for (int i = 0; i < 16; i++) {
            float s = (c0 + i < valid) ? sc[i]*scale : NEGV;
            sc[i] = s;
            mymax = fmaxf(mymax, s);
        }
        mymax = fmaxf(mymax, __shfl_xor_sync(0xffffffffu, mymax, 1));
        mymax = fmaxf(mymax, __shfl_xor_sync(0xffffffffu, mymax, 2));
        float mnew  = fmaxf(m_r, mymax);
        float alpha = __expf(m_r - mnew);
        float psum = 0.f;
        #pragma unroll
        for (int i = 0; i < 16; i++) {
            float p = __expf(sc[i] - mnew);
            ps[r*P_STR + c0 + i] = p;
            psum += p;
        }
        psum += __shfl_xor_sync(0xffffffffu, psum, 1);
        psum += __shfl_xor_sync(0xffffffffu, psum, 2);
        l_r = l_r*alpha + psum;
        m_r = mnew;
        #pragma unroll
        for (int j = 0; j < 24; j++) acc[j] *= alpha;
        __syncwarp();

        // ---- out += P @ V (24 cols per thread) ----
        #pragma unroll 4
        for (int kk = 0; kk < 64; kk++) {
            float p = ps[r*P_STR + kk];
            const float* vr = &vs[kk*V_STR + vcol];
            float4 v0 = *(const float4*)(vr);
            float4 v1 = *(const float4*)(vr+4);
            float4 v2 = *(const float4*)(vr+8);
            float4 v3 = *(const float4*)(vr+12);
            float4 v4 = *(const float4*)(vr+16);
            float4 v5 = *(const float4*)(vr+20);
            acc[0] += p*v0.x; acc[1] += p*v0.y; acc[2] += p*v0.z; acc[3] += p*v0.w;
            acc[4] += p*v1.x; acc[5] += p*v1.y; acc[6] += p*v1.z; acc[7] += p*v1.w;
            acc[8] += p*v2.x; acc[9] += p*v2.y; acc[10]+= p*v2.z; acc[11]+= p*v2.w;
            acc[12]+= p*v3.x; acc[13]+= p*v3.y; acc[14]+= p*v3.z; acc[15]+= p*v3.w;
            acc[16]+= p*v4.x; acc[17]+= p*v4.y; acc[18]+= p*v4.z; acc[19]+= p*v4.w;
            acc[20]+= p*v5.x; acc[21]+= p*v5.y; acc[22]+= p*v5.z; acc[23]+= p*v5.w;
        }
    }

    if (q0 + r < cntb) {
        float inv = 1.f / l_r;
        float* og = O + ((size_t)(b*NS)+q0+r)*ND + h*NHD + vcol;
        #pragma unroll
        for (int j = 0; j < 24; j += 4) {
            *(float4*)(og+j) = make_float4(acc[j]*inv, acc[j+1]*inv, acc[j+2]*inv, acc[j+3]*inv);
        }
    }
}

// ---------------- launch ------------------------------------------------------
extern "C" void kernel_launch(void* const* d_in, const int* in_sizes, int n_in,
                              void* d_out, int out_size)
{
    const float* hs  = (const float*)d_in[0];
    const void*  am  = d_in[1];
    const float* lng = (const float*)d_in[2];
    const float* lnb = (const float*)d_in[3];
    const float* Wq  = (const float*)d_in[4];
    const float* bq  = (const float*)d_in[5];
    const float* Wk  = (const float*)d_in[6];
    const float* bk  = (const float*)d_in[7];
    const float* Wv  = (const float*)d_in[8];
    const float* bv  = (const float*)d_in[9];
    const float* Wo  = (const float*)d_in[10];
    const float* bo  = (const float*)d_in[11];
    float* out = (float*)d_out;

    float *xn, *q, *k, *v, *ao;
    cudaGetSymbolAddress((void**)&xn, g_xn);
    cudaGetSymbolAddress((void**)&q,  g_q);
    cudaGetSymbolAddress((void**)&k,  g_k);
    cudaGetSymbolAddress((void**)&v,  g_v);
    cudaGetSymbolAddress((void**)&ao, g_ao);

    cudaFuncSetAttribute(attn_kernel, cudaFuncAttributeMaxDynamicSharedMemorySize,
                         ATT_SMEM_FLOATS * 4);

    detect_mask_kernel<<<1, 1>>>((const unsigned char*)am);
    compact_kernel<<<NB, 256>>>(am);
    zero_kernel<<<(NM*ND)/(256*4), 256>>>((float4*)out);
    ln_kernel<<<NM, 256>>>(hs, lng, lnb, xn);

    dim3 gqkv(ND/BN, NM/BM, 3);
    gemm_nt<<<gqkv, 256>>>(xn, Wq, bq, q, Wk, bk, k, Wv, bv, v, 0);

    attn_kernel<<<dim3(NS/64, NH, NB), 256, ATT_SMEM_FLOATS*4>>>(q, k, v, ao);

    dim3 go(ND/BN, NM/BM, 1);
    gemm_nt<<<go, 256>>>(ao, Wo, bo, out, Wo, bo, out, Wo, bo, out, 1);
}

// round 5
// speedup vs baseline: 3.2618x; 1.1026x over previous
#include <cuda_runtime.h>
#include <cuda_bf16.h>
#include <math.h>
#include <stdint.h>

#define NB 4
#define NS 2048
#define ND 768
#define NH 8
#define NHD 96
#define NM (NB*NS)
#define NEGV (-1e9f)

// ---------------- scratch (device globals; no allocations allowed) ----------
__device__ __align__(16) __nv_bfloat16 g_ah[NM*ND];   // LN out hi
__device__ __align__(16) __nv_bfloat16 g_al[NM*ND];   // LN out lo
__device__ __align__(16) __nv_bfloat16 g_oh[NM*ND];   // attn out hi
__device__ __align__(16) __nv_bfloat16 g_ol[NM*ND];   // attn out lo
__device__ __align__(16) __nv_bfloat16 g_wh[4*ND*ND]; // W hi (q,k,v,o)
__device__ __align__(16) __nv_bfloat16 g_wl[4*ND*ND]; // W lo
__device__ float g_q[NM*ND];
__device__ float g_k[NM*ND];
__device__ float g_v[NM*ND];
__device__ int   g_idx[NM];
__device__ int   g_cnt[NB];
__device__ int   g_mask_kind;

// ---------------- PTX helpers: ldmatrix + mma.sync (baseline PTX, sm_103-safe)
__device__ __forceinline__ uint32_t smem_u32(const void* p) {
    uint32_t a;
    asm("{ .reg .u64 t; cvta.to.shared.u64 t, %1; cvt.u32.u64 %0, t; }" : "=r"(a) : "l"(p));
    return a;
}
__device__ __forceinline__ void ldsm4(uint32_t& r0, uint32_t& r1, uint32_t& r2, uint32_t& r3, uint32_t a) {
    asm volatile("ldmatrix.sync.aligned.m8n8.x4.shared.b16 {%0,%1,%2,%3}, [%4];"
                 : "=r"(r0), "=r"(r1), "=r"(r2), "=r"(r3) : "r"(a));
}
__device__ __forceinline__ void ldsm2(uint32_t& r0, uint32_t& r1, uint32_t a) {
    asm volatile("ldmatrix.sync.aligned.m8n8.x2.shared.b16 {%0,%1}, [%2];"
                 : "=r"(r0), "=r"(r1) : "r"(a));
}
__device__ __forceinline__ void mma_bf16(float* c, const uint32_t* a, const uint32_t* b) {
    asm volatile(
        "mma.sync.aligned.m16n8k16.row.col.f32.bf16.bf16.f32 "
        "{%0,%1,%2,%3}, {%4,%5,%6,%7}, {%8,%9}, {%0,%1,%2,%3};"
        : "+f"(c[0]), "+f"(c[1]), "+f"(c[2]), "+f"(c[3])
        : "r"(a[0]), "r"(a[1]), "r"(a[2]), "r"(a[3]), "r"(b[0]), "r"(b[1]));
}

__device__ __forceinline__ void split_store(__nv_bfloat16* ph, __nv_bfloat16* pl, float x) {
    __nv_bfloat16 h = __float2bfloat16(x);
    float hf = __bfloat162float(h);
    *ph = h;
    *pl = __float2bfloat16(x - hf);
}

// ---------------- mask dtype detection --------------------------------------
__device__ __forceinline__ float mask_val(const void* m, int i) {
    int kind = g_mask_kind;
    if (kind == 0) return ((const unsigned char*)m)[i] ? 1.f : 0.f;
    if (kind == 1) return ((const int*)m)[i]          ? 1.f : 0.f;
    return (((const float*)m)[i] != 0.f)              ? 1.f : 0.f;
}
__global__ void detect_mask_kernel(const unsigned char* __restrict__ p) {
    if (threadIdx.x != 0 || blockIdx.x != 0) return;
    int has1 = 0, has23 = 0;
    for (int i = 0; i < 4096; i += 4) {
        if (p[i+1]) has1 = 1;
        if (p[i+2] | p[i+3]) has23 = 1;
    }
    g_mask_kind = has1 ? 0 : (has23 ? 2 : 1);
}

// ---------------- compaction -------------------------------------------------
__global__ __launch_bounds__(256) void compact_kernel(const void* __restrict__ mask) {
    int b = blockIdx.x;
    int tid = threadIdx.x;
    int base = b * NS;
    int s0 = tid * 8;
    int bits[8];
    int c = 0;
    #pragma unroll
    for (int e = 0; e < 8; e++) {
        bits[e] = (mask_val(mask, base + s0 + e) != 0.f) ? 1 : 0;
        c += bits[e];
    }
    int lane = tid & 31, w = tid >> 5;
    int v = c;
    #pragma unroll
    for (int o = 1; o < 32; o <<= 1) {
        int t = __shfl_up_sync(0xffffffffu, v, o);
        if (lane >= o) v += t;
    }
    __shared__ int ws[8];
    if (lane == 31) ws[w] = v;
    __syncthreads();
    int wbase = 0;
    for (int i = 0; i < w; i++) wbase += ws[i];
    int p = wbase + v - c;
    #pragma unroll
    for (int e = 0; e < 8; e++) {
        if (bits[e]) g_idx[base + p++] = s0 + e;
    }
    if (tid == 255) g_cnt[b] = p;
}

// ---------------- zero output ------------------------------------------------
__global__ __launch_bounds__(256) void zero_kernel(float4* __restrict__ out) {
    out[(size_t)blockIdx.x * 256 + threadIdx.x] = make_float4(0.f, 0.f, 0.f, 0.f);
}

// ---------------- weight split: fp32 -> bf16 hi/lo ---------------------------
__global__ __launch_bounds__(256) void wsplit_kernel(
    const float* __restrict__ Wq, const float* __restrict__ Wk,
    const float* __restrict__ Wv, const float* __restrict__ Wo)
{
    int i = blockIdx.x * 256 + threadIdx.x;
    const float* Ws[4] = {Wq, Wk, Wv, Wo};
    #pragma unroll
    for (int z = 0; z < 4; z++) {
        float w = Ws[z][i];
        split_store(&g_wh[(size_t)z*ND*ND + i], &g_wl[(size_t)z*ND*ND + i], w);
    }
}

// ---------------- LayerNorm + gather + split ---------------------------------
__global__ __launch_bounds__(256) void ln_kernel(
    const float* __restrict__ x, const float* __restrict__ g,
    const float* __restrict__ b)
{
    int slot = blockIdx.x;
    int bb = slot >> 11, j = slot & (NS-1);
    if (j >= g_cnt[bb]) return;
    int src = (bb << 11) + g_idx[slot];
    const float* xr = x + (size_t)src*ND;
    size_t base = (size_t)slot*ND;
    int t = threadIdx.x;
    float v0 = xr[t], v1 = xr[t+256], v2 = xr[t+512];
    float s  = v0+v1+v2;
    float sq = v0*v0+v1*v1+v2*v2;
    #pragma unroll
    for (int o = 16; o > 0; o >>= 1) {
        s  += __shfl_xor_sync(0xffffffffu, s,  o);
        sq += __shfl_xor_sync(0xffffffffu, sq, o);
    }
    __shared__ float ss[8], sqq[8];
    __shared__ float smu, srs;
    int w = t >> 5;
    if ((t & 31) == 0) { ss[w] = s; sqq[w] = sq; }
    __syncthreads();
    if (t == 0) {
        float S = 0.f, Q = 0.f;
        #pragma unroll
        for (int i = 0; i < 8; i++) { S += ss[i]; Q += sqq[i]; }
        float mu  = S * (1.f/ND);
        float var = Q * (1.f/ND) - mu*mu;
        smu = mu; srs = rsqrtf(var + 1e-5f);
    }
    __syncthreads();
    float mu = smu, rs = srs;
    float y0 = (v0-mu)*rs*g[t]     + b[t];
    float y1 = (v1-mu)*rs*g[t+256] + b[t+256];
    float y2 = (v2-mu)*rs*g[t+512] + b[t+512];
    split_store(&g_ah[base+t],     &g_al[base+t],     y0);
    split_store(&g_ah[base+t+256], &g_al[base+t+256], y1);
    split_store(&g_ah[base+t+512], &g_al[base+t+512], y2);
}

// ---------------- mma.sync bf16x3 GEMM ---------------------------------------
// C[slot 128 x n 128 tile] = A @ W^T + bias. A,W given as bf16 (hi,lo).
// 256 threads = 8 warps (2 m x 4 n), warp tile 64x32, BK=32.
// NT layout: A rows [m][k], W rows [n][k] -> mma row.col, ldmatrix no trans.
#define GSTR 40   // smem row stride in bf16 (80B: conflict-free ldmatrix)

__global__ __launch_bounds__(256, 1) void gemm_mma(
    const __nv_bfloat16* __restrict__ Ah, const __nv_bfloat16* __restrict__ Al,
    int wbase,
    const float* __restrict__ B0, const float* __restrict__ B1, const float* __restrict__ B2,
    float* __restrict__ C0, float* __restrict__ C1, float* __restrict__ C2,
    int scatter)
{
    int z = blockIdx.z;
    const float* bias = (z == 0) ? B0 : (z == 1) ? B1 : B2;
    float*       C    = (z == 0) ? C0 : (z == 1) ? C1 : C2;
    const __nv_bfloat16* Wh = g_wh + (size_t)(wbase + z)*ND*ND;
    const __nv_bfloat16* Wl = g_wl + (size_t)(wbase + z)*ND*ND;

    int bm = blockIdx.y * 128, bn = blockIdx.x * 128;
    int bb = bm >> 11, j0 = bm & (NS-1);
    int cntb = g_cnt[bb];
    if (j0 >= cntb) return;

    __shared__ __align__(16) __nv_bfloat16 Ash[128*GSTR];
    __shared__ __align__(16) __nv_bfloat16 Asl[128*GSTR];
    __shared__ __align__(16) __nv_bfloat16 Bsh[128*GSTR];
    __shared__ __align__(16) __nv_bfloat16 Bsl[128*GSTR];

    int tid = threadIdx.x, lane = tid & 31, wid = tid >> 5;
    int warp_m = wid >> 2;         // 0..1
    int warp_n = wid & 3;          // 0..3

    // global load coords: row = tid/2 (0..127), half = (tid&1)*16 bf16
    int grow = tid >> 1;
    int gcol = (tid & 1) << 4;
    int jr = min(j0 + grow, cntb - 1);
    const __nv_bfloat16* agp = Ah + (size_t)((bb<<11) + jr)*ND + gcol;
    const __nv_bfloat16* alp = Al + (size_t)((bb<<11) + jr)*ND + gcol;
    const __nv_bfloat16* wgp = Wh + (size_t)(bn + grow)*ND + gcol;
    const __nv_bfloat16* wlp = Wl + (size_t)(bn + grow)*ND + gcol;
    __nv_bfloat16* sa_h = &Ash[grow*GSTR + gcol];
    __nv_bfloat16* sa_l = &Asl[grow*GSTR + gcol];
    __nv_bfloat16* sb_h = &Bsh[grow*GSTR + gcol];
    __nv_bfloat16* sb_l = &Bsl[grow*GSTR + gcol];

    // ldmatrix smem addresses (fixed per lane, advance by k-step col offset)
    int a_row = warp_m*64 + (lane & 15);
    int a_col = (lane >> 4) << 3;
    int b_row = warp_n*32 + (lane & 7);
    int b_col = ((lane >> 3) & 1) << 3;
    uint32_t a_h_base = smem_u32(&Ash[a_row*GSTR + a_col]);
    uint32_t a_l_base = smem_u32(&Asl[a_row*GSTR + a_col]);
    uint32_t b_h_base = smem_u32(&Bsh[b_row*GSTR + b_col]);
    uint32_t b_l_base = smem_u32(&Bsl[b_row*GSTR + b_col]);

    float acc[4][4][4];
    #pragma unroll
    for (int mi = 0; mi < 4; mi++)
        #pragma unroll
        for (int ni = 0; ni < 4; ni++)
            #pragma unroll
            for (int e = 0; e < 4; e++) acc[mi][ni][e] = 0.f;

    for (int kc = 0; kc < ND/32; kc++) {
        int kb = kc * 32;
        __syncthreads();
        *(uint4*)(sa_h)     = *(const uint4*)(agp + kb);
        *(uint4*)(sa_h + 8) = *(const uint4*)(agp + kb + 8);
        *(uint4*)(sa_l)     = *(const uint4*)(alp + kb);
        *(uint4*)(sa_l + 8) = *(const uint4*)(alp + kb + 8);
        *(uint4*)(sb_h)     = *(const uint4*)(wgp + kb);
        *(uint4*)(sb_h + 8) = *(const uint4*)(wgp + kb + 8);
        *(uint4*)(sb_l)     = *(const uint4*)(wlp + kb);
        *(uint4*)(sb_l + 8) = *(const uint4*)(wlp + kb + 8);
        __syncthreads();

        #pragma unroll
        for (int ks = 0; ks < 32; ks += 16) {
            uint32_t ah[4][4], al[4][4], bh[4][2], bl[4][2];
            #pragma unroll
            for (int mi = 0; mi < 4; mi++) {
                uint32_t off = (uint32_t)((mi*16*GSTR + ks) * 2);
                ldsm4(ah[mi][0], ah[mi][1], ah[mi][2], ah[mi][3], a_h_base + off);
                ldsm4(al[mi][0], al[mi][1], al[mi][2], al[mi][3], a_l_base + off);
            }
            #pragma unroll
            for (int ni = 0; ni < 4; ni++) {
                uint32_t off = (uint32_t)((ni*8*GSTR + ks) * 2);
                ldsm2(bh[ni][0], bh[ni][1], b_h_base + off);
                ldsm2(bl[ni][0], bl[ni][1], b_l_base + off);
            }
            #pragma unroll
            for (int mi = 0; mi < 4; mi++)
                #pragma unroll
                for (int ni = 0; ni < 4; ni++) {
                    mma_bf16(acc[mi][ni], ah[mi], bh[ni]);
                    mma_bf16(acc[mi][ni], ah[mi], bl[ni]);
                    mma_bf16(acc[mi][ni], al[mi], bh[ni]);
                }
        }
    }

    // ---- epilogue: C frag -> global with bias (+ optional scatter) ----
    int r4 = lane >> 2, c2 = (lane & 3) << 1;
    #pragma unroll
    for (int mi = 0; mi < 4; mi++) {
        #pragma unroll
        for (int half = 0; half < 2; half++) {
            int j = j0 + warp_m*64 + mi*16 + r4 + half*8;
            int doit = 1;
            int orow = (bb << 11) + j;
            if (scatter) {
                doit = (j < cntb);
                if (doit) orow = (bb << 11) + g_idx[(bb << 11) + j];
            }
            if (doit) {
                float* cr = C + (size_t)orow*ND;
                #pragma unroll
                for (int ni = 0; ni < 4; ni++) {
                    int n0 = bn + warp_n*32 + ni*8 + c2;
                    float2 v;
                    v.x = acc[mi][ni][half*2+0] + bias[n0];
                    v.y = acc[mi][ni][half*2+1] + bias[n0+1];
                    *(float2*)(cr + n0) = v;
                }
            }
        }
    }
}

// ---------------- Flash-style attention on compacted rows --------------------
#define Q_STR 100
#define KT_STR 68
#define V_STR 100
#define P_STR 65
#define OFF_Q  0
#define OFF_KT (64*Q_STR)
#define OFF_V  (OFF_KT + NHD*KT_STR)
#define OFF_P  (OFF_V + 64*V_STR)
#define ATT_SMEM_FLOATS (OFF_P + 64*P_STR)

__global__ __launch_bounds__(256) void attn_kernel(
    const float* __restrict__ Q, const float* __restrict__ K,
    const float* __restrict__ V)
{
    extern __shared__ __align__(16) float smf[];
    float* qs = smf + OFF_Q;
    float* kT = smf + OFF_KT;
    float* vs = smf + OFF_V;
    float* ps = smf + OFF_P;

    int tid = threadIdx.x;
    int qt = blockIdx.x, h = blockIdx.y, b = blockIdx.z;
    int cntb = g_cnt[b];
    int q0 = qt*64;
    if (q0 >= cntb) return;
    int ktiles = (cntb + 63) >> 6;

    int r  = tid >> 2;
    int cq = tid & 3;
    int c0 = cq << 4;
    int vcol = cq * 24;

    const float* qg = Q + ((size_t)(b*NS)+q0)*ND + h*NHD;
    for (int f = tid; f < 64*24; f += 256) {
        int rr = f/24, c4 = (f%24)<<2;
        *(float4*)&qs[rr*Q_STR + c4] = *(const float4*)(qg + (size_t)rr*ND + c4);
    }

    float m_r = -INFINITY, l_r = 0.f;
    float acc[24];
    #pragma unroll
    for (int j = 0; j < 24; j++) acc[j] = 0.f;
    const float scale = 0.1020620726159658f;

    for (int kt = 0; kt < ktiles; kt++) {
        int k0 = kt*64;
        int valid = cntb - k0;
        __syncthreads();
        const float* kg = K + ((size_t)(b*NS)+k0)*ND + h*NHD;
        const float* vg = V + ((size_t)(b*NS)+k0)*ND + h*NHD;
        for (int f = tid; f < 64*24; f += 256) {
            int rr = f/24, c4 = (f%24)<<2;
            float4 kv = *(const float4*)(kg + (size_t)rr*ND + c4);
            kT[(c4+0)*KT_STR + rr] = kv.x;
            kT[(c4+1)*KT_STR + rr] = kv.y;
            kT[(c4+2)*KT_STR + rr] = kv.z;
            kT[(c4+3)*KT_STR + rr] = kv.w;
            *(float4*)&vs[rr*V_STR + c4] = *(const float4*)(vg + (size_t)rr*ND + c4);
        }
        __syncthreads();

        float sc[16];
        #pragma unroll
        for (int i = 0; i < 16; i++) sc[i] = 0.f;
        #pragma unroll
        for (int d = 0; d < NHD; d += 4) {
            float4 qv = *(const float4*)&qs[r*Q_STR + d];
            #pragma unroll
            for (int j = 0; j < 4; j++) {
                float qd = (j==0)?qv.x:(j==1)?qv.y:(j==2)?qv.z:qv.w;
                const float* kr = &kT[(d+j)*KT_STR + c0];
                float4 k0v = *(const float4*)(kr);
                float4 k1v = *(const float4*)(kr+4);
                float4 k2v = *(const float4*)(kr+8);
                float4 k3v = *(const float4*)(kr+12);
                sc[0] += qd*k0v.x; sc[1] += qd*k0v.y; sc[2] += qd*k0v.z; sc[3] += qd*k0v.w;
                sc[4] += qd*k1v.x; sc[5] += qd*k1v.y; sc[6] += qd*k1v.z; sc[7] += qd*k1v.w;
                sc[8] += qd*k2v.x; sc[9] += qd*k2v.y; sc[10]+= qd*k2v.z; sc[11]+= qd*k2v.w;
                sc[12]+= qd*k3v.x; sc[13]+= qd*k3v.y; sc[14]+= qd*k3v.z; sc[15]+= qd*k3v.w;
            }
        }

        float mymax = -INFINITY;
        #pragma unroll
        for (int i = 0; i < 16; i++) {
            float s = (c0 + i < valid) ? sc[i]*scale : NEGV;
            sc[i] = s;
            mymax = fmaxf(mymax, s);
        }
        mymax = fmaxf(mymax, __shfl_xor_sync(0xffffffffu, mymax, 1));
        mymax = fmaxf(mymax, __shfl_xor_sync(0xffffffffu, mymax, 2));
        float mnew  = fmaxf(m_r, mymax);
        float alpha = __expf(m_r - mnew);
        float psum = 0.f;
        #pragma unroll
        for (int i = 0; i < 16; i++) {
            float p = __expf(sc[i] - mnew);
            ps[r*P_STR + c0 + i] = p;
            psum += p;
        }
        psum += __shfl_xor_sync(0xffffffffu, psum, 1);
        psum += __shfl_xor_sync(0xffffffffu, psum, 2);
        l_r = l_r*alpha + psum;
        m_r = mnew;
        #pragma unroll
        for (int j = 0; j < 24; j++) acc[j] *= alpha;
        __syncwarp();

        #pragma unroll 4
        for (int kk = 0; kk < 64; kk++) {
            float p = ps[r*P_STR + kk];
            const float* vr = &vs[kk*V_STR + vcol];
            float4 v0 = *(const float4*)(vr);
            float4 v1 = *(const float4*)(vr+4);
            float4 v2 = *(const float4*)(vr+8);
            float4 v3 = *(const float4*)(vr+12);
            float4 v4 = *(const float4*)(vr+16);
            float4 v5 = *(const float4*)(vr+20);
            acc[0] += p*v0.x; acc[1] += p*v0.y; acc[2] += p*v0.z; acc[3] += p*v0.w;
            acc[4] += p*v1.x; acc[5] += p*v1.y; acc[6] += p*v1.z; acc[7] += p*v1.w;
            acc[8] += p*v2.x; acc[9] += p*v2.y; acc[10]+= p*v2.z; acc[11]+= p*v2.w;
            acc[12]+= p*v3.x; acc[13]+= p*v3.y; acc[14]+= p*v3.z; acc[15]+= p*v3.w;
            acc[16]+= p*v4.x; acc[17]+= p*v4.y; acc[18]+= p*v4.z; acc[19]+= p*v4.w;
            acc[20]+= p*v5.x; acc[21]+= p*v5.y; acc[22]+= p*v5.z; acc[23]+= p*v5.w;
        }
    }

    if (q0 + r < cntb) {
        float inv = 1.f / l_r;
        size_t base = ((size_t)(b*NS)+q0+r)*ND + h*NHD + vcol;
        #pragma unroll
        for (int j = 0; j < 24; j += 2) {
            float x0 = acc[j]*inv, x1 = acc[j+1]*inv;
            __nv_bfloat16 h0 = __float2bfloat16(x0);
            __nv_bfloat16 h1 = __float2bfloat16(x1);
            __nv_bfloat162 hh; hh.x = h0; hh.y = h1;
            __nv_bfloat162 ll;
            ll.x = __float2bfloat16(x0 - __bfloat162float(h0));
            ll.y = __float2bfloat16(x1 - __bfloat162float(h1));
            *(__nv_bfloat162*)&g_oh[base + j] = hh;
            *(__nv_bfloat162*)&g_ol[base + j] = ll;
        }
    }
}

// ---------------- launch ------------------------------------------------------
extern "C" void kernel_launch(void* const* d_in, const int* in_sizes, int n_in,
                              void* d_out, int out_size)
{
    const float* hs  = (const float*)d_in[0];
    const void*  am  = d_in[1];
    const float* lng = (const float*)d_in[2];
    const float* lnb = (const float*)d_in[3];
    const float* Wq  = (const float*)d_in[4];
    const float* bq  = (const float*)d_in[5];
    const float* Wk  = (const float*)d_in[6];
    const float* bk  = (const float*)d_in[7];
    const float* Wv  = (const float*)d_in[8];
    const float* bv  = (const float*)d_in[9];
    const float* Wo  = (const float*)d_in[10];
    const float* bo  = (const float*)d_in[11];
    float* out = (float*)d_out;

    __nv_bfloat16 *ah, *al, *oh, *ol;
    float *q, *k, *v;
    cudaGetSymbolAddress((void**)&ah, g_ah);
    cudaGetSymbolAddress((void**)&al, g_al);
    cudaGetSymbolAddress((void**)&oh, g_oh);
    cudaGetSymbolAddress((void**)&ol, g_ol);
    cudaGetSymbolAddress((void**)&q,  g_q);
    cudaGetSymbolAddress((void**)&k,  g_k);
    cudaGetSymbolAddress((void**)&v,  g_v);

    cudaFuncSetAttribute(attn_kernel, cudaFuncAttributeMaxDynamicSharedMemorySize,
                         ATT_SMEM_FLOATS * 4);

    detect_mask_kernel<<<1, 1>>>((const unsigned char*)am);
    compact_kernel<<<NB, 256>>>(am);
    zero_kernel<<<(NM*ND)/(256*4), 256>>>((float4*)out);
    wsplit_kernel<<<(ND*ND)/256, 256>>>(Wq, Wk, Wv, Wo);
    ln_kernel<<<NM, 256>>>(hs, lng, lnb);

    // QKV: A = LN(hi/lo), W slots 0..2
    gemm_mma<<<dim3(ND/128, NM/128, 3), 256>>>(
        ah, al, 0, bq, bk, bv, q, k, v, 0);

    attn_kernel<<<dim3(NS/64, NH, NB), 256, ATT_SMEM_FLOATS*4>>>(q, k, v);

    // O-proj: A = attn out (hi/lo), W slot 3, scatter to d_out
    gemm_mma<<<dim3(ND/128, NM/128, 1), 256>>>(
        oh, ol, 3, bo, bo, bo, out, out, out, 1);
}

// round 6
// speedup vs baseline: 8.1577x; 2.5010x over previous
#include <cuda_runtime.h>
#include <cuda_bf16.h>
#include <math.h>
#include <stdint.h>

#define NB 4
#define NS 2048
#define ND 768
#define NH 8
#define NHD 96
#define NM (NB*NS)
#define NEGV (-1e9f)

// ---------------- scratch (device globals; no allocations allowed) ----------
__device__ __align__(16) __nv_bfloat16 g_ah[NM*ND];   // LN out hi
__device__ __align__(16) __nv_bfloat16 g_al[NM*ND];   // LN out lo
__device__ __align__(16) __nv_bfloat16 g_oh[NM*ND];   // attn out hi
__device__ __align__(16) __nv_bfloat16 g_ol[NM*ND];   // attn out lo
__device__ __align__(16) __nv_bfloat16 g_wh[4*ND*ND]; // W hi (q,k,v,o)
__device__ __align__(16) __nv_bfloat16 g_wl[4*ND*ND]; // W lo
__device__ float g_q[NM*ND];
__device__ float g_k[NM*ND];
__device__ float g_v[NM*ND];
__device__ int   g_idx[NM];
__device__ int   g_cnt[NB];
__device__ int   g_mask_kind;

// ---------------- PTX helpers: ldmatrix + mma.sync (baseline PTX, sm_103-safe)
__device__ __forceinline__ uint32_t smem_u32(const void* p) {
    uint32_t a;
    asm("{ .reg .u64 t; cvta.to.shared.u64 t, %1; cvt.u32.u64 %0, t; }" : "=r"(a) : "l"(p));
    return a;
}
__device__ __forceinline__ void ldsm4(uint32_t& r0, uint32_t& r1, uint32_t& r2, uint32_t& r3, uint32_t a) {
    asm volatile("ldmatrix.sync.aligned.m8n8.x4.shared.b16 {%0,%1,%2,%3}, [%4];"
                 : "=r"(r0), "=r"(r1), "=r"(r2), "=r"(r3) : "r"(a));
}
__device__ __forceinline__ void ldsm2(uint32_t& r0, uint32_t& r1, uint32_t a) {
    asm volatile("ldmatrix.sync.aligned.m8n8.x2.shared.b16 {%0,%1}, [%2];"
                 : "=r"(r0), "=r"(r1) : "r"(a));
}
__device__ __forceinline__ void mma_bf16(float* c, const uint32_t* a, const uint32_t* b) {
    asm volatile(
        "mma.sync.aligned.m16n8k16.row.col.f32.bf16.bf16.f32 "
        "{%0,%1,%2,%3}, {%4,%5,%6,%7}, {%8,%9}, {%0,%1,%2,%3};"
        : "+f"(c[0]), "+f"(c[1]), "+f"(c[2]), "+f"(c[3])
        : "r"(a[0]), "r"(a[1]), "r"(a[2]), "r"(a[3]), "r"(b[0]), "r"(b[1]));
}
__device__ __forceinline__ void mma_bf16_b2(float* c, const uint32_t* a, uint32_t b0, uint32_t b1) {
    asm volatile(
        "mma.sync.aligned.m16n8k16.row.col.f32.bf16.bf16.f32 "
        "{%0,%1,%2,%3}, {%4,%5,%6,%7}, {%8,%9}, {%0,%1,%2,%3};"
        : "+f"(c[0]), "+f"(c[1]), "+f"(c[2]), "+f"(c[3])
        : "r"(a[0]), "r"(a[1]), "r"(a[2]), "r"(a[3]), "r"(b0), "r"(b1));
}

__device__ __forceinline__ void split_store(__nv_bfloat16* ph, __nv_bfloat16* pl, float x) {
    __nv_bfloat16 h = __float2bfloat16(x);
    float hf = __bfloat162float(h);
    *ph = h;
    *pl = __float2bfloat16(x - hf);
}
__device__ __forceinline__ void packsplit(float x0, float x1, uint32_t& h, uint32_t& l) {
    __nv_bfloat162 hh = __floats2bfloat162_rn(x0, x1);
    __nv_bfloat162 ll = __floats2bfloat162_rn(x0 - __bfloat162float(hh.x),
                                              x1 - __bfloat162float(hh.y));
    h = *(uint32_t*)&hh;
    l = *(uint32_t*)&ll;
}

// ---------------- mask dtype detection --------------------------------------
__device__ __forceinline__ float mask_val(const void* m, int i) {
    int kind = g_mask_kind;
    if (kind == 0) return ((const unsigned char*)m)[i] ? 1.f : 0.f;
    if (kind == 1) return ((const int*)m)[i]          ? 1.f : 0.f;
    return (((const float*)m)[i] != 0.f)              ? 1.f : 0.f;
}
__global__ void detect_mask_kernel(const unsigned char* __restrict__ p) {
    if (threadIdx.x != 0 || blockIdx.x != 0) return;
    int has1 = 0, has23 = 0;
    for (int i = 0; i < 4096; i += 4) {
        if (p[i+1]) has1 = 1;
        if (p[i+2] | p[i+3]) has23 = 1;
    }
    g_mask_kind = has1 ? 0 : (has23 ? 2 : 1);
}

// ---------------- compaction -------------------------------------------------
__global__ __launch_bounds__(256) void compact_kernel(const void* __restrict__ mask) {
    int b = blockIdx.x;
    int tid = threadIdx.x;
    int base = b * NS;
    int s0 = tid * 8;
    int bits[8];
    int c = 0;
    #pragma unroll
    for (int e = 0; e < 8; e++) {
        bits[e] = (mask_val(mask, base + s0 + e) != 0.f) ? 1 : 0;
        c += bits[e];
    }
    int lane = tid & 31, w = tid >> 5;
    int v = c;
    #pragma unroll
    for (int o = 1; o < 32; o <<= 1) {
        int t = __shfl_up_sync(0xffffffffu, v, o);
        if (lane >= o) v += t;
    }
    __shared__ int ws[8];
    if (lane == 31) ws[w] = v;
    __syncthreads();
    int wbase = 0;
    for (int i = 0; i < w; i++) wbase += ws[i];
    int p = wbase + v - c;
    #pragma unroll
    for (int e = 0; e < 8; e++) {
        if (bits[e]) g_idx[base + p++] = s0 + e;
    }
    if (tid == 255) g_cnt[b] = p;
}

// ---------------- zero output ------------------------------------------------
__global__ __launch_bounds__(256) void zero_kernel(float4* __restrict__ out) {
    out[(size_t)blockIdx.x * 256 + threadIdx.x] = make_float4(0.f, 0.f, 0.f, 0.f);
}

// ---------------- weight split: fp32 -> bf16 hi/lo ---------------------------
__global__ __launch_bounds__(256) void wsplit_kernel(
    const float* __restrict__ Wq, const float* __restrict__ Wk,
    const float* __restrict__ Wv, const float* __restrict__ Wo)
{
    int i = blockIdx.x * 256 + threadIdx.x;
    const float* Ws[4] = {Wq, Wk, Wv, Wo};
    #pragma unroll
    for (int z = 0; z < 4; z++) {
        float w = Ws[z][i];
        split_store(&g_wh[(size_t)z*ND*ND + i], &g_wl[(size_t)z*ND*ND + i], w);
    }
}

// ---------------- LayerNorm + gather + split ---------------------------------
__global__ __launch_bounds__(256) void ln_kernel(
    const float* __restrict__ x, const float* __restrict__ g,
    const float* __restrict__ b)
{
    int slot = blockIdx.x;
    int bb = slot >> 11, j = slot & (NS-1);
    if (j >= g_cnt[bb]) return;
    int src = (bb << 11) + g_idx[slot];
    const float* xr = x + (size_t)src*ND;
    size_t base = (size_t)slot*ND;
    int t = threadIdx.x;
    float v0 = xr[t], v1 = xr[t+256], v2 = xr[t+512];
    float s  = v0+v1+v2;
    float sq = v0*v0+v1*v1+v2*v2;
    #pragma unroll
    for (int o = 16; o > 0; o >>= 1) {
        s  += __shfl_xor_sync(0xffffffffu, s,  o);
        sq += __shfl_xor_sync(0xffffffffu, sq, o);
    }
    __shared__ float ss[8], sqq[8];
    __shared__ float smu, srs;
    int w = t >> 5;
    if ((t & 31) == 0) { ss[w] = s; sqq[w] = sq; }
    __syncthreads();
    if (t == 0) {
        float S = 0.f, Q = 0.f;
        #pragma unroll
        for (int i = 0; i < 8; i++) { S += ss[i]; Q += sqq[i]; }
        float mu  = S * (1.f/ND);
        float var = Q * (1.f/ND) - mu*mu;
        smu = mu; srs = rsqrtf(var + 1e-5f);
    }
    __syncthreads();
    float mu = smu, rs = srs;
    float y0 = (v0-mu)*rs*g[t]     + b[t];
    float y1 = (v1-mu)*rs*g[t+256] + b[t+256];
    float y2 = (v2-mu)*rs*g[t+512] + b[t+512];
    split_store(&g_ah[base+t],     &g_al[base+t],     y0);
    split_store(&g_ah[base+t+256], &g_al[base+t+256], y1);
    split_store(&g_ah[base+t+512], &g_al[base+t+512], y2);
}

// ---------------- mma.sync bf16x3 GEMM (unchanged from R5) -------------------
#define GSTR 40

__global__ __launch_bounds__(256, 1) void gemm_mma(
    const __nv_bfloat16* __restrict__ Ah, const __nv_bfloat16* __restrict__ Al,
    int wbase,
    const float* __restrict__ B0, const float* __restrict__ B1, const float* __restrict__ B2,
    float* __restrict__ C0, float* __restrict__ C1, float* __restrict__ C2,
    int scatter)
{
    int z = blockIdx.z;
    const float* bias = (z == 0) ? B0 : (z == 1) ? B1 : B2;
    float*       C    = (z == 0) ? C0 : (z == 1) ? C1 : C2;
    const __nv_bfloat16* Wh = g_wh + (size_t)(wbase + z)*ND*ND;
    const __nv_bfloat16* Wl = g_wl + (size_t)(wbase + z)*ND*ND;

    int bm = blockIdx.y * 128, bn = blockIdx.x * 128;
    int bb = bm >> 11, j0 = bm & (NS-1);
    int cntb = g_cnt[bb];
    if (j0 >= cntb) return;

    __shared__ __align__(16) __nv_bfloat16 Ash[128*GSTR];
    __shared__ __align__(16) __nv_bfloat16 Asl[128*GSTR];
    __shared__ __align__(16) __nv_bfloat16 Bsh[128*GSTR];
    __shared__ __align__(16) __nv_bfloat16 Bsl[128*GSTR];

    int tid = threadIdx.x, lane = tid & 31, wid = tid >> 5;
    int warp_m = wid >> 2;
    int warp_n = wid & 3;

    int grow = tid >> 1;
    int gcol = (tid & 1) << 4;
    int jr = min(j0 + grow, cntb - 1);
    const __nv_bfloat16* agp = Ah + (size_t)((bb<<11) + jr)*ND + gcol;
    const __nv_bfloat16* alp = Al + (size_t)((bb<<11) + jr)*ND + gcol;
    const __nv_bfloat16* wgp = Wh + (size_t)(bn + grow)*ND + gcol;
    const __nv_bfloat16* wlp = Wl + (size_t)(bn + grow)*ND + gcol;
    __nv_bfloat16* sa_h = &Ash[grow*GSTR + gcol];
    __nv_bfloat16* sa_l = &Asl[grow*GSTR + gcol];
    __nv_bfloat16* sb_h = &Bsh[grow*GSTR + gcol];
    __nv_bfloat16* sb_l = &Bsl[grow*GSTR + gcol];

    int a_row = warp_m*64 + (lane & 15);
    int a_col = (lane >> 4) << 3;
    int b_row = warp_n*32 + (lane & 7);
    int b_col = ((lane >> 3) & 1) << 3;
    uint32_t a_h_base = smem_u32(&Ash[a_row*GSTR + a_col]);
    uint32_t a_l_base = smem_u32(&Asl[a_row*GSTR + a_col]);
    uint32_t b_h_base = smem_u32(&Bsh[b_row*GSTR + b_col]);
    uint32_t b_l_base = smem_u32(&Bsl[b_row*GSTR + b_col]);

    float acc[4][4][4];
    #pragma unroll
    for (int mi = 0; mi < 4; mi++)
        #pragma unroll
        for (int ni = 0; ni < 4; ni++)
            #pragma unroll
            for (int e = 0; e < 4; e++) acc[mi][ni][e] = 0.f;

    for (int kc = 0; kc < ND/32; kc++) {
        int kb = kc * 32;
        __syncthreads();
        *(uint4*)(sa_h)     = *(const uint4*)(agp + kb);
        *(uint4*)(sa_h + 8) = *(const uint4*)(agp + kb + 8);
        *(uint4*)(sa_l)     = *(const uint4*)(alp + kb);
        *(uint4*)(sa_l + 8) = *(const uint4*)(alp + kb + 8);
        *(uint4*)(sb_h)     = *(const uint4*)(wgp + kb);
        *(uint4*)(sb_h + 8) = *(const uint4*)(wgp + kb + 8);
        *(uint4*)(sb_l)     = *(const uint4*)(wlp + kb);
        *(uint4*)(sb_l + 8) = *(const uint4*)(wlp + kb + 8);
        __syncthreads();

        #pragma unroll
        for (int ks = 0; ks < 32; ks += 16) {
            uint32_t ah[4][4], al[4][4], bh[4][2], bl[4][2];
            #pragma unroll
            for (int mi = 0; mi < 4; mi++) {
                uint32_t off = (uint32_t)((mi*16*GSTR + ks) * 2);
                ldsm4(ah[mi][0], ah[mi][1], ah[mi][2], ah[mi][3], a_h_base + off);
                ldsm4(al[mi][0], al[mi][1], al[mi][2], al[mi][3], a_l_base + off);
            }
            #pragma unroll
            for (int ni = 0; ni < 4; ni++) {
                uint32_t off = (uint32_t)((ni*8*GSTR + ks) * 2);
                ldsm2(bh[ni][0], bh[ni][1], b_h_base + off);
                ldsm2(bl[ni][0], bl[ni][1], b_l_base + off);
            }
            #pragma unroll
            for (int mi = 0; mi < 4; mi++)
                #pragma unroll
                for (int ni = 0; ni < 4; ni++) {
                    mma_bf16(acc[mi][ni], ah[mi], bh[ni]);
                    mma_bf16(acc[mi][ni], ah[mi], bl[ni]);
                    mma_bf16(acc[mi][ni], al[mi], bh[ni]);
                }
        }
    }

    int r4 = lane >> 2, c2 = (lane & 3) << 1;
    #pragma unroll
    for (int mi = 0; mi < 4; mi++) {
        #pragma unroll
        for (int half = 0; half < 2; half++) {
            int j = j0 + warp_m*64 + mi*16 + r4 + half*8;
            int doit = 1;
            int orow = (bb << 11) + j;
            if (scatter) {
                doit = (j < cntb);
                if (doit) orow = (bb << 11) + g_idx[(bb << 11) + j];
            }
            if (doit) {
                float* cr = C + (size_t)orow*ND;
                #pragma unroll
                for (int ni = 0; ni < 4; ni++) {
                    int n0 = bn + warp_n*32 + ni*8 + c2;
                    float2 v;
                    v.x = acc[mi][ni][half*2+0] + bias[n0];
                    v.y = acc[mi][ni][half*2+1] + bias[n0+1];
                    *(float2*)(cr + n0) = v;
                }
            }
        }
    }
}

// ---------------- HMMA flash attention on compacted rows ---------------------
// 128 threads = 4 warps; each warp owns 16 q rows x full 64-key tile.
// Q,K hi/lo bf16 in smem (stride 104), V transposed d-major (stride 72).
#define AQ_STR 104
#define AV_STR 72
#define AOF_QH 0
#define AOF_QL 13312
#define AOF_KH 26624
#define AOF_KL 39936
#define AOF_VH 53248
#define AOF_VL 67072
#define ATT_SMEM 80896

__global__ __launch_bounds__(128) void attn_kernel(
    const float* __restrict__ Q, const float* __restrict__ K,
    const float* __restrict__ V)
{
    extern __shared__ __align__(16) char smc[];
    __nv_bfloat16* QH = (__nv_bfloat16*)(smc + AOF_QH);
    __nv_bfloat16* QL = (__nv_bfloat16*)(smc + AOF_QL);
    __nv_bfloat16* KH = (__nv_bfloat16*)(smc + AOF_KH);
    __nv_bfloat16* KL = (__nv_bfloat16*)(smc + AOF_KL);
    __nv_bfloat16* VH = (__nv_bfloat16*)(smc + AOF_VH);
    __nv_bfloat16* VL = (__nv_bfloat16*)(smc + AOF_VL);

    int tid = threadIdx.x, lane = tid & 31, warp = tid >> 5;
    int qt = blockIdx.x, hd = blockIdx.y, b = blockIdx.z;
    int cntb = g_cnt[b];
    int q0 = qt * 64;
    if (q0 >= cntb) return;
    int ktiles = (cntb + 63) >> 6;
    const float scale = 0.1020620726159658f; // 1/sqrt(96)

    // ---- load Q tile (64 x 96 fp32 -> hi/lo bf16 smem) ----
    const float* qg = Q + ((size_t)(b*NS) + q0)*ND + hd*NHD;
    for (int f = tid; f < 64*24; f += 128) {
        int rr = f/24, c4 = (f%24) << 2;
        float4 qv = *(const float4*)(qg + (size_t)rr*ND + c4);
        uint32_t h0, l0, h1, l1;
        packsplit(qv.x, qv.y, h0, l0);
        packsplit(qv.z, qv.w, h1, l1);
        *(uint32_t*)&QH[rr*AQ_STR + c4]     = h0;
        *(uint32_t*)&QH[rr*AQ_STR + c4 + 2] = h1;
        *(uint32_t*)&QL[rr*AQ_STR + c4]     = l0;
        *(uint32_t*)&QL[rr*AQ_STR + c4 + 2] = l1;
    }

    // ldsm bases
    uint32_t qh_b = smem_u32(&QH[(warp*16 + (lane & 15))*AQ_STR + ((lane >> 4) << 3)]);
    uint32_t ql_b = qh_b + (AOF_QL - AOF_QH);
    uint32_t kh_b = smem_u32(&KH[(lane & 15)*AQ_STR + ((lane >> 4) << 3)]);
    uint32_t kl_b = kh_b + (AOF_KL - AOF_KH);
    uint32_t vh_b = smem_u32(&VH[(lane & 15)*AV_STR + ((lane >> 4) << 3)]);
    uint32_t vl_b = vh_b + (AOF_VL - AOF_VH);

    float acc[12][4];
    #pragma unroll
    for (int nf = 0; nf < 12; nf++)
        #pragma unroll
        for (int e = 0; e < 4; e++) acc[nf][e] = 0.f;
    float m_[2] = {-INFINITY, -INFINITY};
    float l_[2] = {0.f, 0.f};

    for (int kt = 0; kt < ktiles; kt++) {
        int k0 = kt * 64;
        int valid = cntb - k0;
        __syncthreads();   // previous tile consumed (covers Q load on kt=0)
        const float* kg = K + ((size_t)(b*NS) + k0)*ND + hd*NHD;
        const float* vg = V + ((size_t)(b*NS) + k0)*ND + hd*NHD;
        for (int f = tid; f < 64*24; f += 128) {
            int rr = f/24, c4 = (f%24) << 2;
            float4 kv = *(const float4*)(kg + (size_t)rr*ND + c4);
            uint32_t h0, l0, h1, l1;
            packsplit(kv.x, kv.y, h0, l0);
            packsplit(kv.z, kv.w, h1, l1);
            *(uint32_t*)&KH[rr*AQ_STR + c4]     = h0;
            *(uint32_t*)&KH[rr*AQ_STR + c4 + 2] = h1;
            *(uint32_t*)&KL[rr*AQ_STR + c4]     = l0;
            *(uint32_t*)&KL[rr*AQ_STR + c4 + 2] = l1;
            float4 vv = *(const float4*)(vg + (size_t)rr*ND + c4);
            // transpose: VH[d][key]
            split_store(&VH[(c4+0)*AV_STR + rr], &VL[(c4+0)*AV_STR + rr], vv.x);
            split_store(&VH[(c4+1)*AV_STR + rr], &VL[(c4+1)*AV_STR + rr], vv.y);
            split_store(&VH[(c4+2)*AV_STR + rr], &VL[(c4+2)*AV_STR + rr], vv.z);
            split_store(&VH[(c4+3)*AV_STR + rr], &VL[(c4+3)*AV_STR + rr], vv.w);
        }
        __syncthreads();

        // ---- S = Q K^T : warp computes 16 x 64 ----
        float sf[8][4];
        #pragma unroll
        for (int nf = 0; nf < 8; nf++)
            #pragma unroll
            for (int e = 0; e < 4; e++) sf[nf][e] = 0.f;

        #pragma unroll
        for (int ks = 0; ks < 6; ks++) {
            uint32_t aq[4], aql[4];
            ldsm4(aq[0], aq[1], aq[2], aq[3], qh_b + ks*32);
            ldsm4(aql[0], aql[1], aql[2], aql[3], ql_b + ks*32);
            #pragma unroll
            for (int np = 0; np < 4; np++) {
                uint32_t kb[4], kbl[4];
                uint32_t off = (uint32_t)((np*16*AQ_STR + ks*16) * 2);
                ldsm4(kb[0], kb[1], kb[2], kb[3], kh_b + off);
                ldsm4(kbl[0], kbl[1], kbl[2], kbl[3], kl_b + off);
                mma_bf16_b2(sf[2*np],   aq,  kb[0],  kb[2]);
                mma_bf16_b2(sf[2*np],   aq,  kbl[0], kbl[2]);
                mma_bf16_b2(sf[2*np],   aql, kb[0],  kb[2]);
                mma_bf16_b2(sf[2*np+1], aq,  kb[1],  kb[3]);
                mma_bf16_b2(sf[2*np+1], aq,  kbl[1], kbl[3]);
                mma_bf16_b2(sf[2*np+1], aql, kb[1],  kb[3]);
            }
        }

        // ---- online softmax per row-half ----
        int cbase = (lane & 3) << 1;
        #pragma unroll
        for (int h = 0; h < 2; h++) {
            float mx = -INFINITY;
            #pragma unroll
            for (int nf = 0; nf < 8; nf++) {
                #pragma unroll
                for (int e = 0; e < 2; e++) {
                    int col = nf*8 + cbase + e;
                    float s = (col < valid) ? sf[nf][2*h+e]*scale : NEGV;
                    sf[nf][2*h+e] = s;
                    mx = fmaxf(mx, s);
                }
            }
            mx = fmaxf(mx, __shfl_xor_sync(0xffffffffu, mx, 1));
            mx = fmaxf(mx, __shfl_xor_sync(0xffffffffu, mx, 2));
            float mnew = fmaxf(m_[h], mx);
            float alpha = __expf(m_[h] - mnew);
            float psum = 0.f;
            #pragma unroll
            for (int nf = 0; nf < 8; nf++) {
                #pragma unroll
                for (int e = 0; e < 2; e++) {
                    float p = __expf(sf[nf][2*h+e] - mnew);
                    sf[nf][2*h+e] = p;
                    psum += p;
                }
            }
            psum += __shfl_xor_sync(0xffffffffu, psum, 1);
            psum += __shfl_xor_sync(0xffffffffu, psum, 2);
            l_[h] = l_[h]*alpha + psum;
            m_[h] = mnew;
            #pragma unroll
            for (int nf = 0; nf < 12; nf++) {
                acc[nf][2*h]   *= alpha;
                acc[nf][2*h+1] *= alpha;
            }
        }

        // ---- O += P V : P from regs (C-frag == A-frag layout) ----
        #pragma unroll
        for (int kg2 = 0; kg2 < 4; kg2++) {
            uint32_t ph[4], pl[4];
            packsplit(sf[2*kg2][0],   sf[2*kg2][1],   ph[0], pl[0]);
            packsplit(sf[2*kg2][2],   sf[2*kg2][3],   ph[1], pl[1]);
            packsplit(sf[2*kg2+1][0], sf[2*kg2+1][1], ph[2], pl[2]);
            packsplit(sf[2*kg2+1][2], sf[2*kg2+1][3], ph[3], pl[3]);
            #pragma unroll
            for (int np = 0; np < 6; np++) {
                uint32_t vb[4], vbl[4];
                uint32_t off = (uint32_t)((np*16*AV_STR + kg2*16) * 2);
                ldsm4(vb[0], vb[1], vb[2], vb[3], vh_b + off);
                ldsm4(vbl[0], vbl[1], vbl[2], vbl[3], vl_b + off);
                mma_bf16_b2(acc[2*np],   ph, vb[0],  vb[2]);
                mma_bf16_b2(acc[2*np],   ph, vbl[0], vbl[2]);
                mma_bf16_b2(acc[2*np],   pl, vb[0],  vb[2]);
                mma_bf16_b2(acc[2*np+1], ph, vb[1],  vb[3]);
                mma_bf16_b2(acc[2*np+1], ph, vbl[1], vbl[3]);
                mma_bf16_b2(acc[2*np+1], pl, vb[1],  vb[3]);
            }
        }
    }

    // ---- normalize + store hi/lo for O-projection ----
    int r4 = lane >> 2, cbase = (lane & 3) << 1;
    #pragma unroll
    for (int h = 0; h < 2; h++) {
        int row = q0 + warp*16 + r4 + 8*h;
        if (row < cntb) {
            float inv = 1.f / l_[h];
            size_t base = ((size_t)(b*NS) + row)*ND + hd*NHD;
            #pragma unroll
            for (int nf = 0; nf < 12; nf++) {
                int col = nf*8 + cbase;
                uint32_t hh, ll;
                packsplit(acc[nf][2*h]*inv, acc[nf][2*h+1]*inv, hh, ll);
                *(uint32_t*)&g_oh[base + col] = hh;
                *(uint32_t*)&g_ol[base + col] = ll;
            }
        }
    }
}

// ---------------- launch ------------------------------------------------------
extern "C" void kernel_launch(void* const* d_in, const int* in_sizes, int n_in,
                              void* d_out, int out_size)
{
    const float* hs  = (const float*)d_in[0];
    const void*  am  = d_in[1];
    const float* lng = (const float*)d_in[2];
    const float* lnb = (const float*)d_in[3];
    const float* Wq  = (const float*)d_in[4];
    const float* bq  = (const float*)d_in[5];
    const float* Wk  = (const float*)d_in[6];
    const float* bk  = (const float*)d_in[7];
    const float* Wv  = (const float*)d_in[8];
    const float* bv  = (const float*)d_in[9];
    const float* Wo  = (const float*)d_in[10];
    const float* bo  = (const float*)d_in[11];
    float* out = (float*)d_out;

    __nv_bfloat16 *ah, *al, *oh, *ol;
    float *q, *k, *v;
    cudaGetSymbolAddress((void**)&ah, g_ah);
    cudaGetSymbolAddress((void**)&al, g_al);
    cudaGetSymbolAddress((void**)&oh, g_oh);
    cudaGetSymbolAddress((void**)&ol, g_ol);
    cudaGetSymbolAddress((void**)&q,  g_q);
    cudaGetSymbolAddress((void**)&k,  g_k);
    cudaGetSymbolAddress((void**)&v,  g_v);

    cudaFuncSetAttribute(attn_kernel, cudaFuncAttributeMaxDynamicSharedMemorySize,
                         ATT_SMEM);

    detect_mask_kernel<<<1, 1>>>((const unsigned char*)am);
    compact_kernel<<<NB, 256>>>(am);
    zero_kernel<<<(NM*ND)/(256*4), 256>>>((float4*)out);
    wsplit_kernel<<<(ND*ND)/256, 256>>>(Wq, Wk, Wv, Wo);
    ln_kernel<<<NM, 256>>>(hs, lng, lnb);

    // QKV: A = LN(hi/lo), W slots 0..2
    gemm_mma<<<dim3(ND/128, NM/128, 3), 256>>>(
        ah, al, 0, bq, bk, bv, q, k, v, 0);

    attn_kernel<<<dim3(NS/64, NH, NB), 128, ATT_SMEM>>>(q, k, v);

    // O-proj: A = attn out (hi/lo), W slot 3, scatter to d_out
    gemm_mma<<<dim3(ND/128, NM/128, 1), 256>>>(
        oh, ol, 3, bo, bo, bo, out, out, out, 1);
}

// round 7
// speedup vs baseline: 11.1000x; 1.3607x over previous
#include <cuda_runtime.h>
#include <cuda_bf16.h>
#include <math.h>
#include <stdint.h>

#define NB 4
#define NS 2048
#define ND 768
#define NH 8
#define NHD 96
#define NM (NB*NS)
#define NEGV (-1e9f)

// ---------------- scratch (device globals; no allocations allowed) ----------
__device__ __align__(16) __nv_bfloat16 g_ah[NM*ND];   // LN out hi
__device__ __align__(16) __nv_bfloat16 g_al[NM*ND];   // LN out lo
__device__ __align__(16) __nv_bfloat16 g_oh[NM*ND];   // attn out hi
__device__ __align__(16) __nv_bfloat16 g_ol[NM*ND];   // attn out lo
__device__ __align__(16) __nv_bfloat16 g_wh[4*ND*ND]; // W hi (q,k,v,o)
__device__ __align__(16) __nv_bfloat16 g_wl[4*ND*ND]; // W lo
__device__ float g_q[NM*ND];
__device__ float g_k[NM*ND];
__device__ float g_v[NM*ND];
__device__ int   g_idx[NM];
__device__ int   g_cnt[NB];
__device__ int   g_mask_kind;

// ---------------- PTX helpers (baseline PTX, sm_103-safe) --------------------
__device__ __forceinline__ uint32_t smem_u32(const void* p) {
    uint32_t a;
    asm("{ .reg .u64 t; cvta.to.shared.u64 t, %1; cvt.u32.u64 %0, t; }" : "=r"(a) : "l"(p));
    return a;
}
__device__ __forceinline__ void ldsm4(uint32_t& r0, uint32_t& r1, uint32_t& r2, uint32_t& r3, uint32_t a) {
    asm volatile("ldmatrix.sync.aligned.m8n8.x4.shared.b16 {%0,%1,%2,%3}, [%4];"
                 : "=r"(r0), "=r"(r1), "=r"(r2), "=r"(r3) : "r"(a));
}
__device__ __forceinline__ void ldsm4t(uint32_t& r0, uint32_t& r1, uint32_t& r2, uint32_t& r3, uint32_t a) {
    asm volatile("ldmatrix.sync.aligned.m8n8.x4.trans.shared.b16 {%0,%1,%2,%3}, [%4];"
                 : "=r"(r0), "=r"(r1), "=r"(r2), "=r"(r3) : "r"(a));
}
__device__ __forceinline__ void ldsm2(uint32_t& r0, uint32_t& r1, uint32_t a) {
    asm volatile("ldmatrix.sync.aligned.m8n8.x2.shared.b16 {%0,%1}, [%2];"
                 : "=r"(r0), "=r"(r1) : "r"(a));
}
__device__ __forceinline__ void mma_bf16(float* c, const uint32_t* a, const uint32_t* b) {
    asm volatile(
        "mma.sync.aligned.m16n8k16.row.col.f32.bf16.bf16.f32 "
        "{%0,%1,%2,%3}, {%4,%5,%6,%7}, {%8,%9}, {%0,%1,%2,%3};"
        : "+f"(c[0]), "+f"(c[1]), "+f"(c[2]), "+f"(c[3])
        : "r"(a[0]), "r"(a[1]), "r"(a[2]), "r"(a[3]), "r"(b[0]), "r"(b[1]));
}
__device__ __forceinline__ void mma_bf16_b2(float* c, const uint32_t* a, uint32_t b0, uint32_t b1) {
    asm volatile(
        "mma.sync.aligned.m16n8k16.row.col.f32.bf16.bf16.f32 "
        "{%0,%1,%2,%3}, {%4,%5,%6,%7}, {%8,%9}, {%0,%1,%2,%3};"
        : "+f"(c[0]), "+f"(c[1]), "+f"(c[2]), "+f"(c[3])
        : "r"(a[0]), "r"(a[1]), "r"(a[2]), "r"(a[3]), "r"(b0), "r"(b1));
}
__device__ __forceinline__ void cp16(uint32_t d, const void* s) {
    asm volatile("cp.async.cg.shared.global [%0], [%1], 16;" :: "r"(d), "l"(s));
}
#define CP_COMMIT() asm volatile("cp.async.commit_group;")

__device__ __forceinline__ void split_store(__nv_bfloat16* ph, __nv_bfloat16* pl, float x) {
    __nv_bfloat16 h = __float2bfloat16(x);
    float hf = __bfloat162float(h);
    *ph = h;
    *pl = __float2bfloat16(x - hf);
}
__device__ __forceinline__ void packsplit(float x0, float x1, uint32_t& h, uint32_t& l) {
    __nv_bfloat162 hh = __floats2bfloat162_rn(x0, x1);
    __nv_bfloat162 ll = __floats2bfloat162_rn(x0 - __bfloat162float(hh.x),
                                              x1 - __bfloat162float(hh.y));
    h = *(uint32_t*)&hh;
    l = *(uint32_t*)&ll;
}

// ---------------- mask dtype detection --------------------------------------
__device__ __forceinline__ float mask_val(const void* m, int i) {
    int kind = g_mask_kind;
    if (kind == 0) return ((const unsigned char*)m)[i] ? 1.f : 0.f;
    if (kind == 1) return ((const int*)m)[i]          ? 1.f : 0.f;
    return (((const float*)m)[i] != 0.f)              ? 1.f : 0.f;
}
__global__ void detect_mask_kernel(const unsigned char* __restrict__ p) {
    if (threadIdx.x != 0 || blockIdx.x != 0) return;
    int has1 = 0, has23 = 0;
    for (int i = 0; i < 4096; i += 4) {
        if (p[i+1]) has1 = 1;
        if (p[i+2] | p[i+3]) has23 = 1;
    }
    g_mask_kind = has1 ? 0 : (has23 ? 2 : 1);
}

// ---------------- compaction -------------------------------------------------
__global__ __launch_bounds__(256) void compact_kernel(const void* __restrict__ mask) {
    int b = blockIdx.x;
    int tid = threadIdx.x;
    int base = b * NS;
    int s0 = tid * 8;
    int bits[8];
    int c = 0;
    #pragma unroll
    for (int e = 0; e < 8; e++) {
        bits[e] = (mask_val(mask, base + s0 + e) != 0.f) ? 1 : 0;
        c += bits[e];
    }
    int lane = tid & 31, w = tid >> 5;
    int v = c;
    #pragma unroll
    for (int o = 1; o < 32; o <<= 1) {
        int t = __shfl_up_sync(0xffffffffu, v, o);
        if (lane >= o) v += t;
    }
    __shared__ int ws[8];
    if (lane == 31) ws[w] = v;
    __syncthreads();
    int wbase = 0;
    for (int i = 0; i < w; i++) wbase += ws[i];
    int p = wbase + v - c;
    #pragma unroll
    for (int e = 0; e < 8; e++) {
        if (bits[e]) g_idx[base + p++] = s0 + e;
    }
    if (tid == 255) g_cnt[b] = p;
}

// ---------------- zero output ------------------------------------------------
__global__ __launch_bounds__(256) void zero_kernel(float4* __restrict__ out) {
    out[(size_t)blockIdx.x * 256 + threadIdx.x] = make_float4(0.f, 0.f, 0.f, 0.f);
}

// ---------------- weight split: fp32 -> bf16 hi/lo ---------------------------
__global__ __launch_bounds__(256) void wsplit_kernel(
    const float* __restrict__ Wq, const float* __restrict__ Wk,
    const float* __restrict__ Wv, const float* __restrict__ Wo)
{
    int i = blockIdx.x * 256 + threadIdx.x;
    const float* Ws[4] = {Wq, Wk, Wv, Wo};
    #pragma unroll
    for (int z = 0; z < 4; z++) {
        float w = Ws[z][i];
        split_store(&g_wh[(size_t)z*ND*ND + i], &g_wl[(size_t)z*ND*ND + i], w);
    }
}

// ---------------- LayerNorm + gather + split ---------------------------------
__global__ __launch_bounds__(256) void ln_kernel(
    const float* __restrict__ x, const float* __restrict__ g,
    const float* __restrict__ b)
{
    int slot = blockIdx.x;
    int bb = slot >> 11, j = slot & (NS-1);
    if (j >= g_cnt[bb]) return;
    int src = (bb << 11) + g_idx[slot];
    const float* xr = x + (size_t)src*ND;
    size_t base = (size_t)slot*ND;
    int t = threadIdx.x;
    float v0 = xr[t], v1 = xr[t+256], v2 = xr[t+512];
    float s  = v0+v1+v2;
    float sq = v0*v0+v1*v1+v2*v2;
    #pragma unroll
    for (int o = 16; o > 0; o >>= 1) {
        s  += __shfl_xor_sync(0xffffffffu, s,  o);
        sq += __shfl_xor_sync(0xffffffffu, sq, o);
    }
    __shared__ float ss[8], sqq[8];
    __shared__ float smu, srs;
    int w = t >> 5;
    if ((t & 31) == 0) { ss[w] = s; sqq[w] = sq; }
    __syncthreads();
    if (t == 0) {
        float S = 0.f, Q = 0.f;
        #pragma unroll
        for (int i = 0; i < 8; i++) { S += ss[i]; Q += sqq[i]; }
        float mu  = S * (1.f/ND);
        float var = Q * (1.f/ND) - mu*mu;
        smu = mu; srs = rsqrtf(var + 1e-5f);
    }
    __syncthreads();
    float mu = smu, rs = srs;
    float y0 = (v0-mu)*rs*g[t]     + b[t];
    float y1 = (v1-mu)*rs*g[t+256] + b[t+256];
    float y2 = (v2-mu)*rs*g[t+512] + b[t+512];
    split_store(&g_ah[base+t],     &g_al[base+t],     y0);
    split_store(&g_ah[base+t+256], &g_al[base+t+256], y1);
    split_store(&g_ah[base+t+512], &g_al[base+t+512], y2);
}

// ---------------- cp.async double-buffered bf16x3 GEMM -----------------------
// 128x128 tile, BK=32, 8 warps (2m x 4n), warp tile 64x32.
#define GSTR 40
#define G_AH 0
#define G_AL 10240
#define G_BH 20480
#define G_BL 30720
#define STG  40960
#define GEMM_SMEM (2*STG)

__global__ __launch_bounds__(256) void gemm_mma(
    const __nv_bfloat16* __restrict__ Ah, const __nv_bfloat16* __restrict__ Al,
    int wbase,
    const float* __restrict__ B0, const float* __restrict__ B1, const float* __restrict__ B2,
    float* __restrict__ C0, float* __restrict__ C1, float* __restrict__ C2,
    int scatter)
{
    int z = blockIdx.z;
    const float* bias = (z == 0) ? B0 : (z == 1) ? B1 : B2;
    float*       C    = (z == 0) ? C0 : (z == 1) ? C1 : C2;
    const __nv_bfloat16* Wh = g_wh + (size_t)(wbase + z)*ND*ND;
    const __nv_bfloat16* Wl = g_wl + (size_t)(wbase + z)*ND*ND;

    int bm = blockIdx.y * 128, bn = blockIdx.x * 128;
    int bb = bm >> 11, j0 = bm & (NS-1);
    int cntb = g_cnt[bb];
    if (j0 >= cntb) return;

    extern __shared__ __align__(16) char gsm[];
    uint32_t sb = smem_u32(gsm);

    int tid = threadIdx.x, lane = tid & 31, wid = tid >> 5;
    int warp_m = wid >> 2;
    int warp_n = wid & 3;

    int grow = tid >> 1;
    int gcol = (tid & 1) << 4;
    int jr = min(j0 + grow, cntb - 1);
    const __nv_bfloat16* agp = Ah + (size_t)((bb<<11) + jr)*ND + gcol;
    const __nv_bfloat16* alp = Al + (size_t)((bb<<11) + jr)*ND + gcol;
    const __nv_bfloat16* wgp = Wh + (size_t)(bn + grow)*ND + gcol;
    const __nv_bfloat16* wlp = Wl + (size_t)(bn + grow)*ND + gcol;
    uint32_t sdst = sb + (uint32_t)((grow*GSTR + gcol) * 2);

    int a_row = warp_m*64 + (lane & 15);
    int a_col = (lane >> 4) << 3;
    int b_row = warp_n*32 + (lane & 7);
    int b_col = ((lane >> 3) & 1) << 3;
    uint32_t ah0 = sb + G_AH + (uint32_t)((a_row*GSTR + a_col) * 2);
    uint32_t bh0 = sb + G_BH + (uint32_t)((b_row*GSTR + b_col) * 2);

    float acc[4][4][4];
    #pragma unroll
    for (int mi = 0; mi < 4; mi++)
        #pragma unroll
        for (int ni = 0; ni < 4; ni++)
            #pragma unroll
            for (int e = 0; e < 4; e++) acc[mi][ni][e] = 0.f;

    const int NK = ND/32;  // 24

    // prologue: stage 0 and 1
    #pragma unroll
    for (int p = 0; p < 2; p++) {
        uint32_t d = sdst + p*STG;
        int kb = p * 32;
        cp16(d + G_AH,      agp + kb); cp16(d + G_AH + 16, agp + kb + 8);
        cp16(d + G_AL,      alp + kb); cp16(d + G_AL + 16, alp + kb + 8);
        cp16(d + G_BH,      wgp + kb); cp16(d + G_BH + 16, wgp + kb + 8);
        cp16(d + G_BL,      wlp + kb); cp16(d + G_BL + 16, wlp + kb + 8);
        CP_COMMIT();
    }

    for (int kc = 0; kc < NK; kc++) {
        uint32_t st = (uint32_t)(kc & 1) * STG;
        if (kc == NK-1) asm volatile("cp.async.wait_group 0;");
        else            asm volatile("cp.async.wait_group 1;");
        __syncthreads();

        uint32_t a_h = ah0 + st, a_l = a_h + (G_AL - G_AH);
        uint32_t b_h = bh0 + st, b_l = b_h + (G_BL - G_BH);
        #pragma unroll
        for (int ks = 0; ks < 32; ks += 16) {
            uint32_t ah[4][4], al[4][4], bh[4][2], bl[4][2];
            #pragma unroll
            for (int mi = 0; mi < 4; mi++) {
                uint32_t off = (uint32_t)((mi*16*GSTR + ks) * 2);
                ldsm4(ah[mi][0], ah[mi][1], ah[mi][2], ah[mi][3], a_h + off);
                ldsm4(al[mi][0], al[mi][1], al[mi][2], al[mi][3], a_l + off);
            }
            #pragma unroll
            for (int ni = 0; ni < 4; ni++) {
                uint32_t off = (uint32_t)((ni*8*GSTR + ks) * 2);
                ldsm2(bh[ni][0], bh[ni][1], b_h + off);
                ldsm2(bl[ni][0], bl[ni][1], b_l + off);
            }
            #pragma unroll
            for (int mi = 0; mi < 4; mi++)
                #pragma unroll
                for (int ni = 0; ni < 4; ni++) {
                    mma_bf16(acc[mi][ni], ah[mi], bh[ni]);
                    mma_bf16(acc[mi][ni], ah[mi], bl[ni]);
                    mma_bf16(acc[mi][ni], al[mi], bh[ni]);
                }
        }
        __syncthreads();
        if (kc + 2 < NK) {
            uint32_t d = sdst + st;
            int kb = (kc + 2) * 32;
            cp16(d + G_AH,      agp + kb); cp16(d + G_AH + 16, agp + kb + 8);
            cp16(d + G_AL,      alp + kb); cp16(d + G_AL + 16, alp + kb + 8);
            cp16(d + G_BH,      wgp + kb); cp16(d + G_BH + 16, wgp + kb + 8);
            cp16(d + G_BL,      wlp + kb); cp16(d + G_BL + 16, wlp + kb + 8);
            CP_COMMIT();
        } else {
            CP_COMMIT();  // keep group count consistent for wait_group 1
        }
    }

    int r4 = lane >> 2, c2 = (lane & 3) << 1;
    #pragma unroll
    for (int mi = 0; mi < 4; mi++) {
        #pragma unroll
        for (int half = 0; half < 2; half++) {
            int j = j0 + warp_m*64 + mi*16 + r4 + half*8;
            int doit = 1;
            int orow = (bb << 11) + j;
            if (scatter) {
                doit = (j < cntb);
                if (doit) orow = (bb << 11) + g_idx[(bb << 11) + j];
            }
            if (doit) {
                float* cr = C + (size_t)orow*ND;
                #pragma unroll
                for (int ni = 0; ni < 4; ni++) {
                    int n0 = bn + warp_n*32 + ni*8 + c2;
                    float2 v;
                    v.x = acc[mi][ni][half*2+0] + bias[n0];
                    v.y = acc[mi][ni][half*2+1] + bias[n0+1];
                    *(float2*)(cr + n0) = v;
                }
            }
        }
    }
}

// ---------------- HMMA flash attention: 128 q rows, 8 warps ------------------
// Q,K,V all row-major hi/lo bf16 smem (stride 104); V consumed via ldmatrix.trans.
#define AQ_STR 104
#define AOF_QH 0
#define AOF_QL 26624
#define AOF_KH 53248
#define AOF_KL 66560
#define AOF_VH 79872
#define AOF_VL 93184
#define ATT_SMEM 106496

__global__ __launch_bounds__(256) void attn_kernel(
    const float* __restrict__ Q, const float* __restrict__ K,
    const float* __restrict__ V)
{
    extern __shared__ __align__(16) char smc[];
    __nv_bfloat16* QH = (__nv_bfloat16*)(smc + AOF_QH);
    __nv_bfloat16* QL = (__nv_bfloat16*)(smc + AOF_QL);
    __nv_bfloat16* KH = (__nv_bfloat16*)(smc + AOF_KH);
    __nv_bfloat16* KL = (__nv_bfloat16*)(smc + AOF_KL);
    __nv_bfloat16* VH = (__nv_bfloat16*)(smc + AOF_VH);
    __nv_bfloat16* VL = (__nv_bfloat16*)(smc + AOF_VL);

    int tid = threadIdx.x, lane = tid & 31, warp = tid >> 5;
    int qt = blockIdx.x, hd = blockIdx.y, b = blockIdx.z;
    int cntb = g_cnt[b];
    int q0 = qt * 128;
    if (q0 >= cntb) return;
    int ktiles = (cntb + 63) >> 6;
    const float scale = 0.1020620726159658f; // 1/sqrt(96)

    // ---- load Q tile (128 x 96 fp32 -> hi/lo bf16 smem) ----
    const float* qg = Q + ((size_t)(b*NS) + q0)*ND + hd*NHD;
    for (int f = tid; f < 128*24; f += 256) {
        int rr = f/24, c4 = (f%24) << 2;
        float4 qv = *(const float4*)(qg + (size_t)rr*ND + c4);
        uint32_t h0, l0, h1, l1;
        packsplit(qv.x, qv.y, h0, l0);
        packsplit(qv.z, qv.w, h1, l1);
        *(uint32_t*)&QH[rr*AQ_STR + c4]     = h0;
        *(uint32_t*)&QH[rr*AQ_STR + c4 + 2] = h1;
        *(uint32_t*)&QL[rr*AQ_STR + c4]     = l0;
        *(uint32_t*)&QL[rr*AQ_STR + c4 + 2] = l1;
    }

    // ldsm bases
    uint32_t qh_b = smem_u32(&QH[(warp*16 + (lane & 15))*AQ_STR + ((lane >> 4) << 3)]);
    uint32_t ql_b = qh_b + (AOF_QL - AOF_QH);
    uint32_t kh_b = smem_u32(&KH[(lane & 15)*AQ_STR + ((lane >> 4) << 3)]);
    uint32_t kl_b = kh_b + (AOF_KL - AOF_KH);
    // trans ldmatrix base for V[key][d]: k = (lane&7) + ((lane>>4)<<3), d8 = ((lane>>3)&1)<<3
    uint32_t vh_b = smem_u32(&VH[((lane & 7) + ((lane >> 4) << 3))*AQ_STR + (((lane >> 3) & 1) << 3)]);
    uint32_t vl_b = vh_b + (AOF_VL - AOF_VH);

    float acc[12][4];
    #pragma unroll
    for (int nf = 0; nf < 12; nf++)
        #pragma unroll
        for (int e = 0; e < 4; e++) acc[nf][e] = 0.f;
    float m_[2] = {-INFINITY, -INFINITY};
    float l_[2] = {0.f, 0.f};

    for (int kt = 0; kt < ktiles; kt++) {
        int k0 = kt * 64;
        int valid = cntb - k0;
        __syncthreads();   // previous tile consumed (covers Q load on kt=0)
        const float* kg = K + ((size_t)(b*NS) + k0)*ND + hd*NHD;
        const float* vg = V + ((size_t)(b*NS) + k0)*ND + hd*NHD;
        for (int f = tid; f < 64*24; f += 256) {
            int rr = f/24, c4 = (f%24) << 2;
            float4 kv = *(const float4*)(kg + (size_t)rr*ND + c4);
            uint32_t h0, l0, h1, l1;
            packsplit(kv.x, kv.y, h0, l0);
            packsplit(kv.z, kv.w, h1, l1);
            *(uint32_t*)&KH[rr*AQ_STR + c4]     = h0;
            *(uint32_t*)&KH[rr*AQ_STR + c4 + 2] = h1;
            *(uint32_t*)&KL[rr*AQ_STR + c4]     = l0;
            *(uint32_t*)&KL[rr*AQ_STR + c4 + 2] = l1;
            float4 vv = *(const float4*)(vg + (size_t)rr*ND + c4);
            packsplit(vv.x, vv.y, h0, l0);
            packsplit(vv.z, vv.w, h1, l1);
            *(uint32_t*)&VH[rr*AQ_STR + c4]     = h0;
            *(uint32_t*)&VH[rr*AQ_STR + c4 + 2] = h1;
            *(uint32_t*)&VL[rr*AQ_STR + c4]     = l0;
            *(uint32_t*)&VL[rr*AQ_STR + c4 + 2] = l1;
        }
        __syncthreads();

        // ---- S = Q K^T : warp computes 16 x 64 ----
        float sf[8][4];
        #pragma unroll
        for (int nf = 0; nf < 8; nf++)
            #pragma unroll
            for (int e = 0; e < 4; e++) sf[nf][e] = 0.f;

        #pragma unroll
        for (int ks = 0; ks < 6; ks++) {
            uint32_t aq[4], aql[4];
            ldsm4(aq[0], aq[1], aq[2], aq[3], qh_b + ks*32);
            ldsm4(aql[0], aql[1], aql[2], aql[3], ql_b + ks*32);
            #pragma unroll
            for (int np = 0; np < 4; np++) {
                uint32_t kb[4], kbl[4];
                uint32_t off = (uint32_t)((np*16*AQ_STR + ks*16) * 2);
                ldsm4(kb[0], kb[1], kb[2], kb[3], kh_b + off);
                ldsm4(kbl[0], kbl[1], kbl[2], kbl[3], kl_b + off);
                mma_bf16_b2(sf[2*np],   aq,  kb[0],  kb[2]);
                mma_bf16_b2(sf[2*np],   aq,  kbl[0], kbl[2]);
                mma_bf16_b2(sf[2*np],   aql, kb[0],  kb[2]);
                mma_bf16_b2(sf[2*np+1], aq,  kb[1],  kb[3]);
                mma_bf16_b2(sf[2*np+1], aq,  kbl[1], kbl[3]);
                mma_bf16_b2(sf[2*np+1], aql, kb[1],  kb[3]);
            }
        }

        // ---- online softmax per row-half ----
        int cbase = (lane & 3) << 1;
        #pragma unroll
        for (int h = 0; h < 2; h++) {
            float mx = -INFINITY;
            #pragma unroll
            for (int nf = 0; nf < 8; nf++) {
                #pragma unroll
                for (int e = 0; e < 2; e++) {
                    int col = nf*8 + cbase + e;
                    float s = (col < valid) ? sf[nf][2*h+e]*scale : NEGV;
                    sf[nf][2*h+e] = s;
                    mx = fmaxf(mx, s);
                }
            }
            mx = fmaxf(mx, __shfl_xor_sync(0xffffffffu, mx, 1));
            mx = fmaxf(mx, __shfl_xor_sync(0xffffffffu, mx, 2));
            float mnew = fmaxf(m_[h], mx);
            float alpha = __expf(m_[h] - mnew);
            float psum = 0.f;
            #pragma unroll
            for (int nf = 0; nf < 8; nf++) {
                #pragma unroll
                for (int e = 0; e < 2; e++) {
                    float p = __expf(sf[nf][2*h+e] - mnew);
                    sf[nf][2*h+e] = p;
                    psum += p;
                }
            }
            psum += __shfl_xor_sync(0xffffffffu, psum, 1);
            psum += __shfl_xor_sync(0xffffffffu, psum, 2);
            l_[h] = l_[h]*alpha + psum;
            m_[h] = mnew;
            #pragma unroll
            for (int nf = 0; nf < 12; nf++) {
                acc[nf][2*h]   *= alpha;
                acc[nf][2*h+1] *= alpha;
            }
        }

        // ---- O += P V : P in regs, V via trans ldmatrix ----
        #pragma unroll
        for (int kg2 = 0; kg2 < 4; kg2++) {
            uint32_t ph[4], pl[4];
            packsplit(sf[2*kg2][0],   sf[2*kg2][1],   ph[0], pl[0]);
            packsplit(sf[2*kg2][2],   sf[2*kg2][3],   ph[1], pl[1]);
            packsplit(sf[2*kg2+1][0], sf[2*kg2+1][1], ph[2], pl[2]);
            packsplit(sf[2*kg2+1][2], sf[2*kg2+1][3], ph[3], pl[3]);
            #pragma unroll
            for (int np = 0; np < 6; np++) {
                uint32_t vb[4], vbl[4];
                uint32_t off = (uint32_t)((kg2*16*AQ_STR + np*16) * 2);
                ldsm4t(vb[0], vb[1], vb[2], vb[3], vh_b + off);
                ldsm4t(vbl[0], vbl[1], vbl[2], vbl[3], vl_b + off);
                mma_bf16_b2(acc[2*np],   ph, vb[0],  vb[2]);
                mma_bf16_b2(acc[2*np],   ph, vbl[0], vbl[2]);
                mma_bf16_b2(acc[2*np],   pl, vb[0],  vb[2]);
                mma_bf16_b2(acc[2*np+1], ph, vb[1],  vb[3]);
                mma_bf16_b2(acc[2*np+1], ph, vbl[1], vbl[3]);
                mma_bf16_b2(acc[2*np+1], pl, vb[1],  vb[3]);
            }
        }
    }

    // ---- normalize + store hi/lo for O-projection ----
    int r4 = lane >> 2, cbase = (lane & 3) << 1;
    #pragma unroll
    for (int h = 0; h < 2; h++) {
        int row = q0 + warp*16 + r4 + 8*h;
        if (row < cntb) {
            float inv = 1.f / l_[h];
            size_t base = ((size_t)(b*NS) + row)*ND + hd*NHD;
            #pragma unroll
            for (int nf = 0; nf < 12; nf++) {
                int col = nf*8 + cbase;
                uint32_t hh, ll;
                packsplit(acc[nf][2*h]*inv, acc[nf][2*h+1]*inv, hh, ll);
                *(uint32_t*)&g_oh[base + col] = hh;
                *(uint32_t*)&g_ol[base + col] = ll;
            }
        }
    }
}

// ---------------- launch ------------------------------------------------------
extern "C" void kernel_launch(void* const* d_in, const int* in_sizes, int n_in,
                              void* d_out, int out_size)
{
    const float* hs  = (const float*)d_in[0];
    const void*  am  = d_in[1];
    const float* lng = (const float*)d_in[2];
    const float* lnb = (const float*)d_in[3];
    const float* Wq  = (const float*)d_in[4];
    const float* bq  = (const float*)d_in[5];
    const float* Wk  = (const float*)d_in[6];
    const float* bk  = (const float*)d_in[7];
    const float* Wv  = (const float*)d_in[8];
    const float* bv  = (const float*)d_in[9];
    const float* Wo  = (const float*)d_in[10];
    const float* bo  = (const float*)d_in[11];
    float* out = (float*)d_out;

    __nv_bfloat16 *ah, *al, *oh, *ol;
    float *q, *k, *v;
    cudaGetSymbolAddress((void**)&ah, g_ah);
    cudaGetSymbolAddress((void**)&al, g_al);
    cudaGetSymbolAddress((void**)&oh, g_oh);
    cudaGetSymbolAddress((void**)&ol, g_ol);
    cudaGetSymbolAddress((void**)&q,  g_q);
    cudaGetSymbolAddress((void**)&k,  g_k);
    cudaGetSymbolAddress((void**)&v,  g_v);

    cudaFuncSetAttribute(attn_kernel, cudaFuncAttributeMaxDynamicSharedMemorySize,
                         ATT_SMEM);
    cudaFuncSetAttribute(gemm_mma, cudaFuncAttributeMaxDynamicSharedMemorySize,
                         GEMM_SMEM);

    detect_mask_kernel<<<1, 1>>>((const unsigned char*)am);
    compact_kernel<<<NB, 256>>>(am);
    zero_kernel<<<(NM*ND)/(256*4), 256>>>((float4*)out);
    wsplit_kernel<<<(ND*ND)/256, 256>>>(Wq, Wk, Wv, Wo);
    ln_kernel<<<NM, 256>>>(hs, lng, lnb);

    // QKV: A = LN(hi/lo), W slots 0..2
    gemm_mma<<<dim3(ND/128, NM/128, 3), 256, GEMM_SMEM>>>(
        ah, al, 0, bq, bk, bv, q, k, v, 0);

    attn_kernel<<<dim3(NS/128, NH, NB), 256, ATT_SMEM>>>(q, k, v);

    // O-proj: A = attn out (hi/lo), W slot 3, scatter to d_out
    gemm_mma<<<dim3(ND/128, NM/128, 1), 256, GEMM_SMEM>>>(
        oh, ol, 3, bo, bo, bo, out, out, out, 1);
}